// round 14
// baseline (speedup 1.0000x reference)
#include <cuda_runtime.h>
#include <math.h>
#include <stdint.h>

#define Bz 2
#define Sz 2048
#define Dz 1024
#define Hz 16
#define HDz 64

// ---------------- scratch (device globals; no allocation allowed) ----------
__device__ float g_ln[Bz * Sz * Dz];            // layernorm output (tf32-rounded)
__device__ float g_q[Bz * Hz * Sz * HDz];       // q in [B,H,S,hd] (tf32-rounded)
__device__ float g_a[Bz * Sz * Dz];             // attention output (tf32-rounded)
__device__ float g_xa[Bz * Sz * Dz];            // x + attn (exact)
__device__ float g_h1[Bz * Sz * 4 * Dz];        // mlp hidden (tf32-rounded)
__device__ float g_wq[Dz * 3 * Dz];             // tf32-rounded weights
__device__ float g_wm[Dz * Dz];
__device__ float g_w1[Dz * 4 * Dz];
__device__ float g_w2[4 * Dz * Dz];
__device__ float g_pm[32 * 16 * Sz];            // per (bh, coltile, row) partial max
__device__ float g_pl[32 * 16 * Sz];            // per (bh, coltile, row) partial sumexp
__device__ float g_M[32 * Sz];                  // per (bh,row) final max
__device__ float g_Li[32 * Sz];                 // per (bh,row) 1/L

// ---------------- helpers ---------------------------------------------------
__device__ __forceinline__ uint32_t f2tf32(float x) {
    uint32_t y;
    asm("cvt.rna.tf32.f32 %0, %1;" : "=r"(y) : "f"(x));
    return y;
}
__device__ __forceinline__ float tfr(float x) { return __uint_as_float(f2tf32(x)); }

__device__ __forceinline__ void mma_tf32(float (&d)[4], const uint32_t (&a)[4], const uint32_t (&b)[2]) {
    asm volatile("mma.sync.aligned.m16n8k8.row.col.f32.tf32.tf32.f32 "
                 "{%0,%1,%2,%3}, {%4,%5,%6,%7}, {%8,%9}, {%0,%1,%2,%3};"
                 : "+f"(d[0]), "+f"(d[1]), "+f"(d[2]), "+f"(d[3])
                 : "r"(a[0]), "r"(a[1]), "r"(a[2]), "r"(a[3]), "r"(b[0]), "r"(b[1]));
}

__device__ __forceinline__ uint32_t s2u(const void* p) {
    return (uint32_t)__cvta_generic_to_shared(p);
}
#define CP16(dst, src) asm volatile("cp.async.cg.shared.global [%0], [%1], 16;\n" :: "r"(dst), "l"(src))
#define CP_COMMIT()    asm volatile("cp.async.commit_group;\n" ::: "memory")

// fast exp on FMA pipe (validated R4/R5/R9: rel_err unchanged)
__device__ __forceinline__ float fexp(float x) {
    float y = fmaxf(x * 1.4426950408889634f, -126.0f);
    float n = floorf(y);
    float f = y - n;
    float p = fmaf(f, 0.0013333558f, 0.0096181291f);
    p = fmaf(f, p, 0.0555041087f);
    p = fmaf(f, p, 0.2402265069f);
    p = fmaf(f, p, 0.6931471806f);
    p = fmaf(f, p, 1.0f);
    float sc = __int_as_float(((int)n + 127) << 23);
    return p * sc;
}

// ---------------- all-weights pre-round to tf32 (single launch) ------------
__global__ void cvtw_all(const float* __restrict__ s0, const float* __restrict__ s1,
                         const float* __restrict__ s2, const float* __restrict__ s3,
                         float* __restrict__ d0, float* __restrict__ d1,
                         float* __restrict__ d2, float* __restrict__ d3) {
    int i = blockIdx.x * 256 + threadIdx.x;
    const float4* s; float4* d; int j = i;
    if (j < 786432) { s = (const float4*)s0; d = (float4*)d0; }
    else if ((j -= 786432) < 262144) { s = (const float4*)s1; d = (float4*)d1; }
    else if ((j -= 262144) < 1048576) { s = (const float4*)s2; d = (float4*)d2; }
    else { j -= 1048576; s = (const float4*)s3; d = (float4*)d3; }
    float4 v = s[j];
    v.x = tfr(v.x); v.y = tfr(v.y); v.z = tfr(v.z); v.w = tfr(v.w);
    d[j] = v;
}

// ---------------- layernorm (tf32-rounded output; feeds GEMMs only) --------
__global__ void layernorm_k(const float* __restrict__ x, const float* __restrict__ g,
                            const float* __restrict__ b, float* __restrict__ y) {
    int row = blockIdx.x;
    int tid = threadIdx.x;
    const float4* xr = (const float4*)(x + (size_t)row * Dz);
    float4 v = xr[tid];
    float s  = v.x + v.y + v.z + v.w;
    float sq = v.x * v.x + v.y * v.y + v.z * v.z + v.w * v.w;

    __shared__ float shs[8], shq[8];
    for (int o = 16; o; o >>= 1) { s += __shfl_xor_sync(0xffffffffu, s, o); sq += __shfl_xor_sync(0xffffffffu, sq, o); }
    int lane = tid & 31, wid = tid >> 5;
    if (lane == 0) { shs[wid] = s; shq[wid] = sq; }
    __syncthreads();
    float ts = 0.f, tq = 0.f;
    #pragma unroll
    for (int i = 0; i < 8; i++) { ts += shs[i]; tq += shq[i]; }
    float mean = ts * (1.0f / Dz);
    float var  = tq * (1.0f / Dz) - mean * mean;
    float rstd = rsqrtf(var + 1e-5f);

    float4 gg = ((const float4*)g)[tid];
    float4 bb = ((const float4*)b)[tid];
    float4 o;
    o.x = tfr((v.x - mean) * rstd * gg.x + bb.x);
    o.y = tfr((v.y - mean) * rstd * gg.y + bb.y);
    o.z = tfr((v.z - mean) * rstd * gg.z + bb.z);
    o.w = tfr((v.w - mean) * rstd * gg.w + bb.w);
    ((float4*)(y + (size_t)row * Dz))[tid] = o;
}

// ---------------- tf32 GEMM, 3-stage cp.async, pre-rounded operands --------
__device__ __forceinline__ void wqkv(float* __restrict__ q, float* __restrict__ pres,
                                     int r, int c, float v) {
    int b = r >> 11, s = r & (Sz - 1);
    int which = c >> 10, rest = c & (Dz - 1);
    int h = rest >> 6, d = rest & 63;
    if (which == 0)
        q[(((size_t)(b * Hz + h) * Sz + s) * HDz) + d] = tfr(v);
    else
        pres[(((size_t)((b * 2 + (which - 1)) * Hz + h) * Sz + s) * HDz) + d] = v;
}

#define GSTG 8960
#define GAs(st, r, c) gsm[(st) * GSTG + (r) * 36 + (c)]
#define GBs(st, k, c) gsm[(st) * GSTG + 4608 + (k) * 136 + (c)]

template <int EPI>  // 0 bias, 1 bias+res, 2 bias+gelu(->tf32), 3 bias+scatter qkv
__global__ __launch_bounds__(256, 2)
void tf32gemm(const float* __restrict__ A, const float* __restrict__ B,
              const float* __restrict__ bias, const float* __restrict__ res,
              float* __restrict__ C, float* __restrict__ qp, float* __restrict__ pp,
              int M, int N, int K, int lda, int ldb, int ldc) {
    extern __shared__ float gsm[];

    int tid = threadIdx.x;
    int row0 = blockIdx.y * 128, col0 = blockIdx.x * 128;

    int arow = tid >> 3;
    int acol = (tid & 7) * 4;
    int brow = tid >> 5;
    int bcol = (tid & 31) * 4;

    int lane = tid & 31, wid = tid >> 5;
    int wm = (wid >> 2) * 64, wn = (wid & 3) * 32;
    int g = lane >> 2, t = lane & 3;

    const float* Abase = A + (size_t)(row0 + arow) * lda + acol;
    const float* Bbase = B + (size_t)brow * ldb + col0 + bcol;

    float acc[16][4];
    #pragma unroll
    for (int i = 0; i < 16; i++)
        #pragma unroll
        for (int j = 0; j < 4; j++) acc[i][j] = 0.f;

    int nst = K >> 5;

    auto issue = [&](int st, int k0) {
        #pragma unroll
        for (int i = 0; i < 4; i++)
            CP16(s2u(&GAs(st, arow + i * 32, acol)), Abase + (size_t)(i * 32) * lda + k0);
        #pragma unroll
        for (int p = 0; p < 4; p++)
            CP16(s2u(&GBs(st, brow + p * 8, bcol)), Bbase + (size_t)(k0 + p * 8) * ldb);
        CP_COMMIT();
    };

    issue(0, 0);
    if (nst > 1) issue(1, 32);

    for (int it = 0; it < nst; it++) {
        int cur = it - (it / 3) * 3;
        if (it + 2 < nst)
            asm volatile("cp.async.wait_group 1;\n" ::: "memory");
        else
            asm volatile("cp.async.wait_group 0;\n" ::: "memory");
        __syncthreads();

        #pragma unroll
        for (int ks = 0; ks < 4; ks++) {
            int k = ks * 8;
            uint32_t afr[4][4], bfr[4][2];
            #pragma unroll
            for (int mi = 0; mi < 4; mi++) {
                int r = wm + mi * 16 + g;
                afr[mi][0] = __float_as_uint(GAs(cur, r, k + t));
                afr[mi][1] = __float_as_uint(GAs(cur, r + 8, k + t));
                afr[mi][2] = __float_as_uint(GAs(cur, r, k + t + 4));
                afr[mi][3] = __float_as_uint(GAs(cur, r + 8, k + t + 4));
            }
            #pragma unroll
            for (int ni = 0; ni < 4; ni++) {
                int c = wn + ni * 8 + g;
                bfr[ni][0] = __float_as_uint(GBs(cur, k + t, c));
                bfr[ni][1] = __float_as_uint(GBs(cur, k + t + 4, c));
            }
            #pragma unroll
            for (int mi = 0; mi < 4; mi++)
                #pragma unroll
                for (int ni = 0; ni < 4; ni++)
                    mma_tf32(acc[mi * 4 + ni], afr[mi], bfr[ni]);
        }

        if (it + 2 < nst) {
            int nx = (it + 2) - ((it + 2) / 3) * 3;
            issue(nx, (it + 2) * 32);
        }
    }

    #pragma unroll
    for (int mi = 0; mi < 4; mi++) {
        #pragma unroll
        for (int ni = 0; ni < 4; ni++) {
            int r = row0 + wm + mi * 16 + g;
            int c = col0 + wn + ni * 8 + t * 2;
            float b0 = bias[c], b1 = bias[c + 1];
            float v0 = acc[mi * 4 + ni][0] + b0;
            float v1 = acc[mi * 4 + ni][1] + b1;
            float v2 = acc[mi * 4 + ni][2] + b0;
            float v3 = acc[mi * 4 + ni][3] + b1;
            if (EPI == 1) {
                v0 += res[(size_t)r * ldc + c];
                v1 += res[(size_t)r * ldc + c + 1];
                v2 += res[(size_t)(r + 8) * ldc + c];
                v3 += res[(size_t)(r + 8) * ldc + c + 1];
            }
            if (EPI == 2) {
                v0 = tfr(0.5f * v0 * (1.0f + erff(v0 * 0.70710678118654752f)));
                v1 = tfr(0.5f * v1 * (1.0f + erff(v1 * 0.70710678118654752f)));
                v2 = tfr(0.5f * v2 * (1.0f + erff(v2 * 0.70710678118654752f)));
                v3 = tfr(0.5f * v3 * (1.0f + erff(v3 * 0.70710678118654752f)));
            }
            if (EPI == 3) {
                wqkv(qp, pp, r, c, v0);
                wqkv(qp, pp, r, c + 1, v1);
                wqkv(qp, pp, r + 8, c, v2);
                wqkv(qp, pp, r + 8, c + 1, v3);
            } else {
                *(float2*)(C + (size_t)r * ldc + c) = make_float2(v0, v1);
                *(float2*)(C + (size_t)(r + 8) * ldc + c) = make_float2(v2, v3);
            }
        }
    }
}

// ---------------- scores + per-tile row stats (raw w written once) ----------
#define QS(r, c) sQ[(r) * 68 + (c)]
#define KS(d, j) sK[(d) * 133 + (j)]
__global__ __launch_bounds__(256)
void scores_mma2(const float* __restrict__ q, const float* __restrict__ present,
                 float* __restrict__ w, float* __restrict__ pm, float* __restrict__ pl) {
    int row0 = blockIdx.y * 128, col0 = blockIdx.x * 128;
    if (col0 > row0 + 127) return;
    int bh = blockIdx.z;
    int b = bh >> 4, h = bh & 15;
    const float* Q  = q + (size_t)bh * Sz * HDz;
    const float* Kd = present + (size_t)((b * 2) * Hz + h) * Sz * HDz;
    float* W = w + (size_t)bh * Sz * Sz;

    extern __shared__ float smem[];
    float* sQ    = smem;                 // 128*68
    float* sK    = sQ + 128 * 68;        // 64*133
    float* sRedM = sK + 64 * 133;        // 512
    float* sRedL = sRedM + 512;          // 512
    float* sMrow = sRedL + 512;          // 128

    int tid = threadIdx.x;
    int lr = tid >> 4;
    int c4 = (tid & 15) * 4;
    #pragma unroll
    for (int i = 0; i < 8; i++) {
        int r = lr + i * 16;
        float4 a = *(const float4*)(Q + (size_t)(row0 + r) * HDz + c4);
        QS(r, c4 + 0) = a.x; QS(r, c4 + 1) = a.y;     // q already tf32-rounded
        QS(r, c4 + 2) = a.z; QS(r, c4 + 3) = a.w;
        float4 kk = *(const float4*)(Kd + (size_t)(col0 + r) * HDz + c4);
        KS(c4 + 0, r) = tfr(kk.x); KS(c4 + 1, r) = tfr(kk.y);
        KS(c4 + 2, r) = tfr(kk.z); KS(c4 + 3, r) = tfr(kk.w);
    }
    __syncthreads();

    int lane = tid & 31, wid = tid >> 5;
    int wm = (wid >> 2) * 64, wn = (wid & 3) * 32, wnI = wid & 3;
    int g = lane >> 2, t = lane & 3;

    float acc[16][4];
    #pragma unroll
    for (int i = 0; i < 16; i++)
        #pragma unroll
        for (int j = 0; j < 4; j++) acc[i][j] = 0.f;

    #pragma unroll
    for (int ks = 0; ks < 8; ks++) {
        int k = ks * 8;
        uint32_t afr[4][4], bfr[4][2];
        #pragma unroll
        for (int mi = 0; mi < 4; mi++) {
            int r = wm + mi * 16 + g;
            afr[mi][0] = __float_as_uint(QS(r, k + t));
            afr[mi][1] = __float_as_uint(QS(r + 8, k + t));
            afr[mi][2] = __float_as_uint(QS(r, k + t + 4));
            afr[mi][3] = __float_as_uint(QS(r + 8, k + t + 4));
        }
        #pragma unroll
        for (int ni = 0; ni < 4; ni++) {
            int c = wn + ni * 8 + g;
            bfr[ni][0] = __float_as_uint(KS(k + t, c));
            bfr[ni][1] = __float_as_uint(KS(k + t + 4, c));
        }
        #pragma unroll
        for (int mi = 0; mi < 4; mi++)
            #pragma unroll
            for (int ni = 0; ni < 4; ni++)
                mma_tf32(acc[mi * 4 + ni], afr[mi], bfr[ni]);
    }

    bool dg = (row0 == col0);
    #pragma unroll
    for (int mi = 0; mi < 4; mi++) {
        #pragma unroll
        for (int ni = 0; ni < 4; ni++) {
            #pragma unroll
            for (int j = 0; j < 4; j++) acc[mi * 4 + ni][j] *= 0.125f;
            int rl0 = wm + mi * 16 + g, rl1 = rl0 + 8;
            int cl = wn + ni * 8 + t * 2;
            *(float2*)(W + (size_t)(row0 + rl0) * Sz + col0 + cl) =
                make_float2(acc[mi * 4 + ni][0], acc[mi * 4 + ni][1]);
            *(float2*)(W + (size_t)(row0 + rl1) * Sz + col0 + cl) =
                make_float2(acc[mi * 4 + ni][2], acc[mi * 4 + ni][3]);
            if (dg) {   // mask register copy for stats only
                if (cl     > rl0) acc[mi * 4 + ni][0] = -1e30f;
                if (cl + 1 > rl0) acc[mi * 4 + ni][1] = -1e30f;
                if (cl     > rl1) acc[mi * 4 + ni][2] = -1e30f;
                if (cl + 1 > rl1) acc[mi * 4 + ni][3] = -1e30f;
            }
        }
    }

    float fm[8];
    #pragma unroll
    for (int mi = 0; mi < 4; mi++) {
        float m0 = -1e30f, m1 = -1e30f;
        #pragma unroll
        for (int ni = 0; ni < 4; ni++) {
            m0 = fmaxf(m0, fmaxf(acc[mi * 4 + ni][0], acc[mi * 4 + ni][1]));
            m1 = fmaxf(m1, fmaxf(acc[mi * 4 + ni][2], acc[mi * 4 + ni][3]));
        }
        fm[mi * 2] = m0; fm[mi * 2 + 1] = m1;
    }
    #pragma unroll
    for (int i = 0; i < 8; i++) {
        fm[i] = fmaxf(fm[i], __shfl_xor_sync(0xffffffffu, fm[i], 1));
        fm[i] = fmaxf(fm[i], __shfl_xor_sync(0xffffffffu, fm[i], 2));
    }
    if (t == 0) {
        #pragma unroll
        for (int mi = 0; mi < 4; mi++) {
            sRedM[wnI * 128 + wm + mi * 16 + g]     = fm[mi * 2];
            sRedM[wnI * 128 + wm + mi * 16 + 8 + g] = fm[mi * 2 + 1];
        }
    }
    __syncthreads();
    if (tid < 128)
        sMrow[tid] = fmaxf(fmaxf(sRedM[tid], sRedM[128 + tid]),
                           fmaxf(sRedM[256 + tid], sRedM[384 + tid]));
    __syncthreads();

    float fs[8];
    #pragma unroll
    for (int mi = 0; mi < 4; mi++) {
        int rl0 = wm + mi * 16 + g, rl1 = rl0 + 8;
        float M0 = sMrow[rl0], M1 = sMrow[rl1];
        float s0 = 0.f, s1 = 0.f;
        #pragma unroll
        for (int ni = 0; ni < 4; ni++) {
            s0 += fexp(acc[mi * 4 + ni][0] - M0) + fexp(acc[mi * 4 + ni][1] - M0);
            s1 += fexp(acc[mi * 4 + ni][2] - M1) + fexp(acc[mi * 4 + ni][3] - M1);
        }
        fs[mi * 2] = s0; fs[mi * 2 + 1] = s1;
    }
    #pragma unroll
    for (int i = 0; i < 8; i++) {
        fs[i] += __shfl_xor_sync(0xffffffffu, fs[i], 1);
        fs[i] += __shfl_xor_sync(0xffffffffu, fs[i], 2);
    }
    if (t == 0) {
        #pragma unroll
        for (int mi = 0; mi < 4; mi++) {
            sRedL[wnI * 128 + wm + mi * 16 + g]     = fs[mi * 2];
            sRedL[wnI * 128 + wm + mi * 16 + 8 + g] = fs[mi * 2 + 1];
        }
    }
    __syncthreads();
    if (tid < 128) {
        float plv = sRedL[tid] + sRedL[128 + tid] + sRedL[256 + tid] + sRedL[384 + tid];
        size_t si = ((size_t)bh * 16 + blockIdx.x) * Sz + row0 + tid;
        pm[si] = sMrow[tid];
        pl[si] = plv;
    }
}

// ---------------- fold partial stats into (M, 1/L) per row ------------------
__global__ void rowstat_k(const float* __restrict__ pm, const float* __restrict__ pl,
                          float* __restrict__ Mv, float* __restrict__ Li) {
    int idx = blockIdx.x * 256 + threadIdx.x;        // bh*Sz + row
    int bh = idx >> 11, row = idx & (Sz - 1);
    int nt = (row >> 7) + 1;
    float M = -1e30f;
    for (int ct = 0; ct < nt; ct++)
        M = fmaxf(M, pm[((size_t)bh * 16 + ct) * Sz + row]);
    float L = 0.f;
    for (int ct = 0; ct < nt; ct++) {
        size_t si = ((size_t)bh * 16 + ct) * Sz + row;
        L += pl[si] * fexp(pm[si] - M);
    }
    Mv[idx] = M;
    Li[idx] = 1.0f / L;
}

// ---------------- A = P @ V; 3-stage cp.async; writes normalized w ---------
#define AST 6912
#define AWs(st, r, c) avsm[(st) * AST + (r) * 36 + (c)]
#define AVs(st, k, c) avsm[(st) * AST + 4608 + (k) * 72 + (c)]

__global__ __launch_bounds__(256, 2)
void av_mma(float* __restrict__ w, const float* __restrict__ present,
            const float* __restrict__ Mv, const float* __restrict__ Li,
            float* __restrict__ a) {
    extern __shared__ float avsm[];
    int bh = blockIdx.z;
    int b = bh >> 4, h = bh & 15;
    int row0 = ((int)gridDim.y - 1 - (int)blockIdx.y) * 128;   // heavy blocks first
    float* W = w + (size_t)bh * Sz * Sz;
    const float* V = present + (size_t)((b * 2 + 1) * Hz + h) * Sz * HDz;
    float* A = a + ((size_t)b * Sz) * Dz + h * HDz;

    int tid = threadIdx.x;
    int lane = tid & 31, wid = tid >> 5;
    int wm = (wid >> 1) * 32, wn = (wid & 1) * 32;
    int g = lane >> 2, t = lane & 3;

    // per-lane stats for the 4 fragment rows
    float Mr[4], Lr[4];
    #pragma unroll
    for (int mi = 0; mi < 2; mi++) {
        int r0 = row0 + wm + mi * 16 + g;
        Mr[mi * 2]     = Mv[bh * Sz + r0];
        Lr[mi * 2]     = Li[bh * Sz + r0];
        Mr[mi * 2 + 1] = Mv[bh * Sz + r0 + 8];
        Lr[mi * 2 + 1] = Li[bh * Sz + r0 + 8];
    }
    // per-thread stats for the w write-out row
    int srow = tid >> 1, shalf = tid & 1;
    float Mst = Mv[bh * Sz + row0 + srow];
    float Lst = Li[bh * Sz + row0 + srow];
    int sgrow = row0 + srow;

    float acc[8][4];
    #pragma unroll
    for (int i = 0; i < 8; i++)
        #pragma unroll
        for (int j = 0; j < 4; j++) acc[i][j] = 0.f;

    int nst = (row0 + 128) >> 5;                 // >= 4 always

    auto issue = [&](int st, int k0) {
        #pragma unroll
        for (int i = 0; i < 4; i++) {
            int idx = tid + i * 256;
            int row = idx >> 3, c16 = (idx & 7) * 4;
            CP16(s2u(&AWs(st, row, c16)), W + (size_t)(row0 + row) * Sz + k0 + c16);
        }
        #pragma unroll
        for (int i = 0; i < 2; i++) {
            int idx = tid + i * 256;
            int row = idx >> 4, c16 = (idx & 15) * 4;
            CP16(s2u(&AVs(st, row, c16)), V + (size_t)(k0 + row) * HDz + c16);
        }
        CP_COMMIT();
    };

    issue(0, 0);
    issue(1, 32);

    for (int it = 0; it < nst; it++) {
        int cur = it - (it / 3) * 3;
        if (it + 2 < nst)
            asm volatile("cp.async.wait_group 1;\n" ::: "memory");
        else
            asm volatile("cp.async.wait_group 0;\n" ::: "memory");
        __syncthreads();
        int k0 = it * 32;

        #pragma unroll
        for (int ks = 0; ks < 4; ks++) {
            int k = ks * 8;
            uint32_t afr[2][4], bfr[4][2];
            #pragma unroll
            for (int mi = 0; mi < 2; mi++) {
                int r = wm + mi * 16 + g;
                int gr0 = row0 + r, gr1 = gr0 + 8;
                int c0 = k0 + k + t, c1 = c0 + 4;
                float p00 = (c0 > gr0) ? 0.f : fexp(AWs(cur, r, k + t)       - Mr[mi * 2])     * Lr[mi * 2];
                float p10 = (c0 > gr1) ? 0.f : fexp(AWs(cur, r + 8, k + t)   - Mr[mi * 2 + 1]) * Lr[mi * 2 + 1];
                float p01 = (c1 > gr0) ? 0.f : fexp(AWs(cur, r, k + t + 4)   - Mr[mi * 2])     * Lr[mi * 2];
                float p11 = (c1 > gr1) ? 0.f : fexp(AWs(cur, r + 8, k + t + 4) - Mr[mi * 2 + 1]) * Lr[mi * 2 + 1];
                afr[mi][0] = f2tf32(p00);
                afr[mi][1] = f2tf32(p10);
                afr[mi][2] = f2tf32(p01);
                afr[mi][3] = f2tf32(p11);
            }
            #pragma unroll
            for (int ni = 0; ni < 4; ni++) {
                int c = wn + ni * 8 + g;
                bfr[ni][0] = f2tf32(AVs(cur, k + t, c));
                bfr[ni][1] = f2tf32(AVs(cur, k + t + 4, c));
            }
            #pragma unroll
            for (int mi = 0; mi < 2; mi++)
                #pragma unroll
                for (int ni = 0; ni < 4; ni++)
                    mma_tf32(acc[mi * 4 + ni], afr[mi], bfr[ni]);
        }

        // write normalized 128x32 tile back to w (coalesced; recompute from raw smem)
        #pragma unroll
        for (int j = 0; j < 4; j++) {
            int c = shalf * 16 + j * 4;
            int gc = k0 + c;
            float4 raw = *(const float4*)&AWs(cur, srow, c);
            float4 p;
            p.x = (gc     > sgrow) ? 0.f : fexp(raw.x - Mst) * Lst;
            p.y = (gc + 1 > sgrow) ? 0.f : fexp(raw.y - Mst) * Lst;
            p.z = (gc + 2 > sgrow) ? 0.f : fexp(raw.z - Mst) * Lst;
            p.w = (gc + 3 > sgrow) ? 0.f : fexp(raw.w - Mst) * Lst;
            *(float4*)(W + (size_t)sgrow * Sz + gc) = p;
        }

        if (it + 2 < nst) {
            int nx = (it + 2) - ((it + 2) / 3) * 3;
            issue(nx, (it + 2) * 32);
        }
    }

    // a feeds merge GEMM's A operand -> store tf32-rounded
    #pragma unroll
    for (int mi = 0; mi < 2; mi++) {
        #pragma unroll
        for (int ni = 0; ni < 4; ni++) {
            int r = row0 + wm + mi * 16 + g;
            int c = wn + ni * 8 + t * 2;
            *(float2*)(A + (size_t)r * Dz + c) =
                make_float2(tfr(acc[mi * 4 + ni][0]), tfr(acc[mi * 4 + ni][1]));
            *(float2*)(A + (size_t)(r + 8) * Dz + c) =
                make_float2(tfr(acc[mi * 4 + ni][2]), tfr(acc[mi * 4 + ni][3]));
        }
    }

    // zero-fill above-diagonal region of these rows
    int cstart = row0 + 128;
    if (cstart < Sz) {
        int w4 = (Sz - cstart) >> 2;
        float4 z4 = make_float4(0.f, 0.f, 0.f, 0.f);
        for (int i = tid; i < 128 * w4; i += 256) {
            int r = i / w4;
            int cc = (i - r * w4) * 4 + cstart;
            *(float4*)(W + (size_t)(row0 + r) * Sz + cc) = z4;
        }
    }
}

// ---------------- host ------------------------------------------------------
extern "C" void kernel_launch(void* const* d_in, const int* in_sizes, int n_in,
                              void* d_out, int out_size) {
    const float* x       = (const float*)d_in[0];
    const float* qkv_w   = (const float*)d_in[1];
    const float* qkv_b   = (const float*)d_in[2];
    const float* merge_w = (const float*)d_in[3];
    const float* merge_b = (const float*)d_in[4];
    const float* mlp1_w  = (const float*)d_in[5];
    const float* mlp1_b  = (const float*)d_in[6];
    const float* mlp2_w  = (const float*)d_in[7];
    const float* mlp2_b  = (const float*)d_in[8];
    const float* n1_g    = (const float*)d_in[9];
    const float* n1_b    = (const float*)d_in[10];
    const float* n2_g    = (const float*)d_in[11];
    const float* n2_b    = (const float*)d_in[12];

    float *ln, *q, *a, *xa, *h1, *wq, *wmm, *w1, *w2, *pm, *pl, *Mv, *Li;
    cudaGetSymbolAddress((void**)&ln, g_ln);
    cudaGetSymbolAddress((void**)&q,  g_q);
    cudaGetSymbolAddress((void**)&a,  g_a);
    cudaGetSymbolAddress((void**)&xa, g_xa);
    cudaGetSymbolAddress((void**)&h1, g_h1);
    cudaGetSymbolAddress((void**)&wq, g_wq);
    cudaGetSymbolAddress((void**)&wmm, g_wm);
    cudaGetSymbolAddress((void**)&w1, g_w1);
    cudaGetSymbolAddress((void**)&w2, g_w2);
    cudaGetSymbolAddress((void**)&pm, g_pm);
    cudaGetSymbolAddress((void**)&pl, g_pl);
    cudaGetSymbolAddress((void**)&Mv, g_M);
    cudaGetSymbolAddress((void**)&Li, g_Li);

    float* out     = (float*)d_out;
    float* xm      = out;
    float* present = out + (size_t)Bz * Sz * Dz;
    float* w       = present + (size_t)Bz * 2 * Hz * Sz * HDz;

    const int M = Bz * Sz;   // 4096
    const int gemmSmem   = 3 * GSTG * 4;                                // 107520 B
    const int scoresSmem = (128 * 68 + 64 * 133 + 512 + 512 + 128) * 4; // 73472 B
    const int avSmem     = 3 * AST * 4;                                 // 82944 B
    static int attrSet = 0;
    if (!attrSet) {
        cudaFuncSetAttribute(tf32gemm<1>, cudaFuncAttributeMaxDynamicSharedMemorySize, gemmSmem);
        cudaFuncSetAttribute(tf32gemm<2>, cudaFuncAttributeMaxDynamicSharedMemorySize, gemmSmem);
        cudaFuncSetAttribute(tf32gemm<3>, cudaFuncAttributeMaxDynamicSharedMemorySize, gemmSmem);
        cudaFuncSetAttribute(scores_mma2, cudaFuncAttributeMaxDynamicSharedMemorySize, scoresSmem);
        cudaFuncSetAttribute(av_mma, cudaFuncAttributeMaxDynamicSharedMemorySize, avSmem);
        attrSet = 1;
    }

    // 0) pre-round all weights to tf32 (single launch)
    cvtw_all<<<(786432 + 262144 + 1048576 + 1048576) / 256, 256>>>(
        qkv_w, merge_w, mlp1_w, mlp2_w, wq, wmm, w1, w2);

    // 1) ln1 (tf32-rounded)
    layernorm_k<<<M, 256>>>(x, n1_g, n1_b, ln);
    // 2) qkv gemm -> scatter q (tf32) + present (exact, output)
    tf32gemm<3><<<dim3(3 * Dz / 128, M / 128), 256, gemmSmem>>>(
        ln, wq, qkv_b, nullptr, nullptr, q, present, M, 3 * Dz, Dz, Dz, 3 * Dz, 3 * Dz);
    // 3) raw scores (written once) + per-tile row stats
    scores_mma2<<<dim3(Sz / 128, Sz / 128, Bz * Hz), 256, scoresSmem>>>(q, present, w, pm, pl);
    // 4) fold stats into (M, 1/L)
    rowstat_k<<<(Bz * Hz * Sz) / 256, 256>>>(pm, pl, Mv, Li);
    // 5) av: normalize w in-place (written once, normalized) + A = P@V + zero-fill
    av_mma<<<dim3(1, Sz / 128, Bz * Hz), 256, avSmem>>>(w, present, Mv, Li, a);
    // 6) merge gemm + residual -> xa (exact)
    tf32gemm<1><<<dim3(Dz / 128, M / 128), 256, gemmSmem>>>(
        a, wmm, merge_b, x, xa, nullptr, nullptr, M, Dz, Dz, Dz, Dz, Dz);
    // 7) ln2 (tf32-rounded)
    layernorm_k<<<M, 256>>>(xa, n2_g, n2_b, ln);
    // 8) mlp1 + gelu -> h1 (tf32-rounded)
    tf32gemm<2><<<dim3(4 * Dz / 128, M / 128), 256, gemmSmem>>>(
        ln, w1, mlp1_b, nullptr, h1, nullptr, nullptr, M, 4 * Dz, Dz, Dz, 4 * Dz, 4 * Dz);
    // 9) mlp2 + residual -> xm (output, exact)
    tf32gemm<1><<<dim3(Dz / 128, M / 128), 256, gemmSmem>>>(
        h1, w2, mlp2_b, xa, xm, nullptr, nullptr, M, Dz, 4 * Dz, 4 * Dz, Dz, Dz);
}

// round 15
// speedup vs baseline: 1.2000x; 1.2000x over previous
#include <cuda_runtime.h>
#include <math.h>
#include <stdint.h>

#define Bz 2
#define Sz 2048
#define Dz 1024
#define Hz 16
#define HDz 64

// ---------------- scratch (device globals; no allocation allowed) ----------
__device__ float g_ln[Bz * Sz * Dz];            // layernorm output (tf32-rounded)
__device__ float g_q[Bz * Hz * Sz * HDz];       // q in [B,H,S,hd] (tf32-rounded)
__device__ float g_a[Bz * Sz * Dz];             // attention output (tf32-rounded)
__device__ float g_xa[Bz * Sz * Dz];            // x + attn (exact)
__device__ float g_h1[Bz * Sz * 4 * Dz];        // mlp hidden (tf32-rounded)
__device__ float g_wq[Dz * 3 * Dz];             // tf32-rounded weights
__device__ float g_wm[Dz * Dz];
__device__ float g_w1[Dz * 4 * Dz];
__device__ float g_w2[4 * Dz * Dz];

// ---------------- helpers ---------------------------------------------------
__device__ __forceinline__ uint32_t f2tf32(float x) {
    uint32_t y;
    asm("cvt.rna.tf32.f32 %0, %1;" : "=r"(y) : "f"(x));
    return y;
}
__device__ __forceinline__ float tfr(float x) { return __uint_as_float(f2tf32(x)); }

__device__ __forceinline__ void mma_tf32(float (&d)[4], const uint32_t (&a)[4], const uint32_t (&b)[2]) {
    asm volatile("mma.sync.aligned.m16n8k8.row.col.f32.tf32.tf32.f32 "
                 "{%0,%1,%2,%3}, {%4,%5,%6,%7}, {%8,%9}, {%0,%1,%2,%3};"
                 : "+f"(d[0]), "+f"(d[1]), "+f"(d[2]), "+f"(d[3])
                 : "r"(a[0]), "r"(a[1]), "r"(a[2]), "r"(a[3]), "r"(b[0]), "r"(b[1]));
}

__device__ __forceinline__ uint32_t s2u(const void* p) {
    return (uint32_t)__cvta_generic_to_shared(p);
}
#define CP16(dst, src) asm volatile("cp.async.cg.shared.global [%0], [%1], 16;\n" :: "r"(dst), "l"(src))
#define CP_COMMIT()    asm volatile("cp.async.commit_group;\n" ::: "memory")

// ---------------- weight pre-round to tf32 ----------------------------------
__global__ void cvtw_k(const float* __restrict__ src, float* __restrict__ dst) {
    int i = blockIdx.x * 256 + threadIdx.x;
    float4 v = ((const float4*)src)[i];
    v.x = tfr(v.x); v.y = tfr(v.y); v.z = tfr(v.z); v.w = tfr(v.w);
    ((float4*)dst)[i] = v;
}

// ---------------- layernorm (tf32-rounded output; feeds GEMMs only) --------
__global__ void layernorm_k(const float* __restrict__ x, const float* __restrict__ g,
                            const float* __restrict__ b, float* __restrict__ y) {
    int row = blockIdx.x;
    int tid = threadIdx.x;
    const float4* xr = (const float4*)(x + (size_t)row * Dz);
    float4 v = xr[tid];
    float s  = v.x + v.y + v.z + v.w;
    float sq = v.x * v.x + v.y * v.y + v.z * v.z + v.w * v.w;

    __shared__ float shs[8], shq[8];
    for (int o = 16; o; o >>= 1) { s += __shfl_xor_sync(0xffffffffu, s, o); sq += __shfl_xor_sync(0xffffffffu, sq, o); }
    int lane = tid & 31, wid = tid >> 5;
    if (lane == 0) { shs[wid] = s; shq[wid] = sq; }
    __syncthreads();
    float ts = 0.f, tq = 0.f;
    #pragma unroll
    for (int i = 0; i < 8; i++) { ts += shs[i]; tq += shq[i]; }
    float mean = ts * (1.0f / Dz);
    float var  = tq * (1.0f / Dz) - mean * mean;
    float rstd = rsqrtf(var + 1e-5f);

    float4 gg = ((const float4*)g)[tid];
    float4 bb = ((const float4*)b)[tid];
    float4 o;
    o.x = tfr((v.x - mean) * rstd * gg.x + bb.x);
    o.y = tfr((v.y - mean) * rstd * gg.y + bb.y);
    o.z = tfr((v.z - mean) * rstd * gg.z + bb.z);
    o.w = tfr((v.w - mean) * rstd * gg.w + bb.w);
    ((float4*)(y + (size_t)row * Dz))[tid] = o;
}

// ---------------- tf32 GEMM, 3-stage cp.async, pre-rounded operands --------
__device__ __forceinline__ void wqkv(float* __restrict__ q, float* __restrict__ pres,
                                     int r, int c, float v) {
    int b = r >> 11, s = r & (Sz - 1);
    int which = c >> 10, rest = c & (Dz - 1);
    int h = rest >> 6, d = rest & 63;
    if (which == 0)
        q[(((size_t)(b * Hz + h) * Sz + s) * HDz) + d] = tfr(v);
    else
        pres[(((size_t)((b * 2 + (which - 1)) * Hz + h) * Sz + s) * HDz) + d] = v;
}

#define GSTG 8960
#define GAs(st, r, c) gsm[(st) * GSTG + (r) * 36 + (c)]
#define GBs(st, k, c) gsm[(st) * GSTG + 4608 + (k) * 136 + (c)]

template <int EPI>  // 0 bias, 1 bias+res, 2 bias+gelu(->tf32), 3 bias+scatter qkv
__global__ __launch_bounds__(256, 2)
void tf32gemm(const float* __restrict__ A, const float* __restrict__ B,
              const float* __restrict__ bias, const float* __restrict__ res,
              float* __restrict__ C, float* __restrict__ qp, float* __restrict__ pp,
              int M, int N, int K, int lda, int ldb, int ldc) {
    extern __shared__ float gsm[];

    int tid = threadIdx.x;
    int row0 = blockIdx.y * 128, col0 = blockIdx.x * 128;

    int arow = tid >> 3;
    int acol = (tid & 7) * 4;
    int brow = tid >> 5;
    int bcol = (tid & 31) * 4;

    int lane = tid & 31, wid = tid >> 5;
    int wm = (wid >> 2) * 64, wn = (wid & 3) * 32;
    int g = lane >> 2, t = lane & 3;

    const float* Abase = A + (size_t)(row0 + arow) * lda + acol;
    const float* Bbase = B + (size_t)brow * ldb + col0 + bcol;

    float acc[16][4];
    #pragma unroll
    for (int i = 0; i < 16; i++)
        #pragma unroll
        for (int j = 0; j < 4; j++) acc[i][j] = 0.f;

    int nst = K >> 5;

    auto issue = [&](int st, int k0) {
        #pragma unroll
        for (int i = 0; i < 4; i++)
            CP16(s2u(&GAs(st, arow + i * 32, acol)), Abase + (size_t)(i * 32) * lda + k0);
        #pragma unroll
        for (int p = 0; p < 4; p++)
            CP16(s2u(&GBs(st, brow + p * 8, bcol)), Bbase + (size_t)(k0 + p * 8) * ldb);
        CP_COMMIT();
    };

    issue(0, 0);
    if (nst > 1) issue(1, 32);

    for (int it = 0; it < nst; it++) {
        int cur = it - (it / 3) * 3;
        if (it + 2 < nst)
            asm volatile("cp.async.wait_group 1;\n" ::: "memory");
        else
            asm volatile("cp.async.wait_group 0;\n" ::: "memory");
        __syncthreads();

        #pragma unroll
        for (int ks = 0; ks < 4; ks++) {
            int k = ks * 8;
            uint32_t afr[4][4], bfr[4][2];
            #pragma unroll
            for (int mi = 0; mi < 4; mi++) {
                int r = wm + mi * 16 + g;
                afr[mi][0] = __float_as_uint(GAs(cur, r, k + t));
                afr[mi][1] = __float_as_uint(GAs(cur, r + 8, k + t));
                afr[mi][2] = __float_as_uint(GAs(cur, r, k + t + 4));
                afr[mi][3] = __float_as_uint(GAs(cur, r + 8, k + t + 4));
            }
            #pragma unroll
            for (int ni = 0; ni < 4; ni++) {
                int c = wn + ni * 8 + g;
                bfr[ni][0] = __float_as_uint(GBs(cur, k + t, c));
                bfr[ni][1] = __float_as_uint(GBs(cur, k + t + 4, c));
            }
            #pragma unroll
            for (int mi = 0; mi < 4; mi++)
                #pragma unroll
                for (int ni = 0; ni < 4; ni++)
                    mma_tf32(acc[mi * 4 + ni], afr[mi], bfr[ni]);
        }

        if (it + 2 < nst) {
            int nx = (it + 2) - ((it + 2) / 3) * 3;
            issue(nx, (it + 2) * 32);
        }
    }

    #pragma unroll
    for (int mi = 0; mi < 4; mi++) {
        #pragma unroll
        for (int ni = 0; ni < 4; ni++) {
            int r = row0 + wm + mi * 16 + g;
            int c = col0 + wn + ni * 8 + t * 2;
            float b0 = bias[c], b1 = bias[c + 1];
            float v0 = acc[mi * 4 + ni][0] + b0;
            float v1 = acc[mi * 4 + ni][1] + b1;
            float v2 = acc[mi * 4 + ni][2] + b0;
            float v3 = acc[mi * 4 + ni][3] + b1;
            if (EPI == 1) {
                v0 += res[(size_t)r * ldc + c];
                v1 += res[(size_t)r * ldc + c + 1];
                v2 += res[(size_t)(r + 8) * ldc + c];
                v3 += res[(size_t)(r + 8) * ldc + c + 1];
            }
            if (EPI == 2) {
                v0 = tfr(0.5f * v0 * (1.0f + erff(v0 * 0.70710678118654752f)));
                v1 = tfr(0.5f * v1 * (1.0f + erff(v1 * 0.70710678118654752f)));
                v2 = tfr(0.5f * v2 * (1.0f + erff(v2 * 0.70710678118654752f)));
                v3 = tfr(0.5f * v3 * (1.0f + erff(v3 * 0.70710678118654752f)));
            }
            if (EPI == 3) {
                wqkv(qp, pp, r, c, v0);
                wqkv(qp, pp, r, c + 1, v1);
                wqkv(qp, pp, r + 8, c, v2);
                wqkv(qp, pp, r + 8, c + 1, v3);
            } else {
                *(float2*)(C + (size_t)r * ldc + c) = make_float2(v0, v1);
                *(float2*)(C + (size_t)(r + 8) * ldc + c) = make_float2(v2, v3);
            }
        }
    }
}

// ---------------- scores; upper-tile blocks zero-fill their tile -----------
#define QS(r, c) sQ[(r) * 68 + (c)]
#define KS(d, j) sK[(d) * 133 + (j)]
__global__ __launch_bounds__(256)
void scores_mma(const float* __restrict__ q, const float* __restrict__ present,
                float* __restrict__ w) {
    int row0 = blockIdx.y * 128, col0 = blockIdx.x * 128;
    int bh = blockIdx.z;
    float* W = w + (size_t)bh * Sz * Sz;
    int tid = threadIdx.x;

    if (col0 > row0 + 127) {
        // strictly-above-diagonal tile: write zeros (softmax no longer does)
        float4 z4 = make_float4(0.f, 0.f, 0.f, 0.f);
        int r = tid >> 3, c = (tid & 7) * 16;    // 32 rows/pass, 8 cols of float4
        #pragma unroll
        for (int i = 0; i < 4; i++) {
            float4* dst = (float4*)(W + (size_t)(row0 + r + i * 32) * Sz + col0 + c);
            dst[0] = z4; dst[1] = z4; dst[2] = z4; dst[3] = z4;
        }
        return;
    }

    int b = bh >> 4, h = bh & 15;
    const float* Q  = q + (size_t)bh * Sz * HDz;
    const float* Kd = present + (size_t)((b * 2) * Hz + h) * Sz * HDz;

    extern __shared__ float smem[];
    float* sQ = smem;
    float* sK = smem + 128 * 68;

    int lr = tid >> 4;
    int c4 = (tid & 15) * 4;
    #pragma unroll
    for (int i = 0; i < 8; i++) {
        int r = lr + i * 16;
        float4 a = *(const float4*)(Q + (size_t)(row0 + r) * HDz + c4);
        QS(r, c4 + 0) = a.x; QS(r, c4 + 1) = a.y;       // q already tf32-rounded
        QS(r, c4 + 2) = a.z; QS(r, c4 + 3) = a.w;
        float4 kk = *(const float4*)(Kd + (size_t)(col0 + r) * HDz + c4);
        KS(c4 + 0, r) = tfr(kk.x); KS(c4 + 1, r) = tfr(kk.y);
        KS(c4 + 2, r) = tfr(kk.z); KS(c4 + 3, r) = tfr(kk.w);
    }
    __syncthreads();

    int lane = tid & 31, wid = tid >> 5;
    int wm = (wid >> 2) * 64, wn = (wid & 3) * 32;
    int g = lane >> 2, t = lane & 3;

    float acc[16][4];
    #pragma unroll
    for (int i = 0; i < 16; i++)
        #pragma unroll
        for (int j = 0; j < 4; j++) acc[i][j] = 0.f;

    #pragma unroll
    for (int ks = 0; ks < 8; ks++) {
        int k = ks * 8;
        uint32_t afr[4][4], bfr[4][2];
        #pragma unroll
        for (int mi = 0; mi < 4; mi++) {
            int r = wm + mi * 16 + g;
            afr[mi][0] = __float_as_uint(QS(r, k + t));
            afr[mi][1] = __float_as_uint(QS(r + 8, k + t));
            afr[mi][2] = __float_as_uint(QS(r, k + t + 4));
            afr[mi][3] = __float_as_uint(QS(r + 8, k + t + 4));
        }
        #pragma unroll
        for (int ni = 0; ni < 4; ni++) {
            int c = wn + ni * 8 + g;
            bfr[ni][0] = __float_as_uint(KS(k + t, c));
            bfr[ni][1] = __float_as_uint(KS(k + t + 4, c));
        }
        #pragma unroll
        for (int mi = 0; mi < 4; mi++)
            #pragma unroll
            for (int ni = 0; ni < 4; ni++)
                mma_tf32(acc[mi * 4 + ni], afr[mi], bfr[ni]);
    }

    #pragma unroll
    for (int mi = 0; mi < 4; mi++) {
        #pragma unroll
        for (int ni = 0; ni < 4; ni++) {
            int r = row0 + wm + mi * 16 + g;
            int c = col0 + wn + ni * 8 + t * 2;
            *(float2*)(W + (size_t)r * Sz + c) =
                make_float2(acc[mi * 4 + ni][0] * 0.125f, acc[mi * 4 + ni][1] * 0.125f);
            *(float2*)(W + (size_t)(r + 8) * Sz + c) =
                make_float2(acc[mi * 4 + ni][2] * 0.125f, acc[mi * 4 + ni][3] * 0.125f);
        }
    }
}

// ---------------- causal softmax; writes only up to row's tile boundary ----
__global__ __launch_bounds__(256)
void softmax_reg(float* __restrict__ w) {
    int row = blockIdx.x;
    int bh  = blockIdx.y;
    float* wr = w + ((size_t)bh * Sz + row) * Sz;
    int n = row + 1;
    int jlim = (((row >> 7) + 1) << 7);      // tile-boundary; beyond is pre-zeroed
    int tid = threadIdx.x;
    int lane = tid & 31, wid = tid >> 5;
    __shared__ float sh[8];

    int j0 = tid * 4, j1 = (tid + 256) * 4;
    float4 z4 = make_float4(0.f, 0.f, 0.f, 0.f);
    float4 v0 = (j0 < n) ? ((const float4*)wr)[tid] : z4;
    float4 v1 = (j1 < n) ? ((const float4*)wr)[tid + 256] : z4;

    float m = -1e30f;
    m = (j0 + 0 < n) ? fmaxf(m, v0.x) : m;
    m = (j0 + 1 < n) ? fmaxf(m, v0.y) : m;
    m = (j0 + 2 < n) ? fmaxf(m, v0.z) : m;
    m = (j0 + 3 < n) ? fmaxf(m, v0.w) : m;
    m = (j1 + 0 < n) ? fmaxf(m, v1.x) : m;
    m = (j1 + 1 < n) ? fmaxf(m, v1.y) : m;
    m = (j1 + 2 < n) ? fmaxf(m, v1.z) : m;
    m = (j1 + 3 < n) ? fmaxf(m, v1.w) : m;
    for (int o = 16; o; o >>= 1) m = fmaxf(m, __shfl_xor_sync(0xffffffffu, m, o));
    if (lane == 0) sh[wid] = m;
    __syncthreads();
    float M = -1e30f;
    #pragma unroll
    for (int i = 0; i < 8; i++) M = fmaxf(M, sh[i]);
    __syncthreads();

    float4 p0, p1;
    p0.x = (j0 + 0 < n) ? __expf(v0.x - M) : 0.f;
    p0.y = (j0 + 1 < n) ? __expf(v0.y - M) : 0.f;
    p0.z = (j0 + 2 < n) ? __expf(v0.z - M) : 0.f;
    p0.w = (j0 + 3 < n) ? __expf(v0.w - M) : 0.f;
    p1.x = (j1 + 0 < n) ? __expf(v1.x - M) : 0.f;
    p1.y = (j1 + 1 < n) ? __expf(v1.y - M) : 0.f;
    p1.z = (j1 + 2 < n) ? __expf(v1.z - M) : 0.f;
    p1.w = (j1 + 3 < n) ? __expf(v1.w - M) : 0.f;

    float s = p0.x + p0.y + p0.z + p0.w + p1.x + p1.y + p1.z + p1.w;
    for (int o = 16; o; o >>= 1) s += __shfl_xor_sync(0xffffffffu, s, o);
    if (lane == 0) sh[wid] = s;
    __syncthreads();
    float S = 0.f;
    #pragma unroll
    for (int i = 0; i < 8; i++) S += sh[i];
    float inv = 1.0f / S;

    p0.x *= inv; p0.y *= inv; p0.z *= inv; p0.w *= inv;
    p1.x *= inv; p1.y *= inv; p1.z *= inv; p1.w *= inv;
    if (j0 < jlim) ((float4*)wr)[tid] = p0;
    if (j1 < jlim) ((float4*)wr)[tid + 256] = p1;
}

// ---------------- A = W @ V via tf32 mma, 3-stage cp.async, heavy-first ----
#define AST 6912
#define AWs(st, r, c) avsm[(st) * AST + (r) * 36 + (c)]
#define AVs(st, k, c) avsm[(st) * AST + 4608 + (k) * 72 + (c)]

__global__ __launch_bounds__(256, 2)
void av_mma(const float* __restrict__ w, const float* __restrict__ present,
            float* __restrict__ a) {
    extern __shared__ float avsm[];
    int bh = blockIdx.z;
    int b = bh >> 4, h = bh & 15;
    int row0 = ((int)gridDim.y - 1 - (int)blockIdx.y) * 128;   // heavy blocks first
    const float* W = w + (size_t)bh * Sz * Sz;
    const float* V = present + (size_t)((b * 2 + 1) * Hz + h) * Sz * HDz;
    float* A = a + ((size_t)b * Sz) * Dz + h * HDz;

    int tid = threadIdx.x;
    int lane = tid & 31, wid = tid >> 5;
    int wm = (wid >> 1) * 32, wn = (wid & 1) * 32;
    int g = lane >> 2, t = lane & 3;

    float acc[8][4];
    #pragma unroll
    for (int i = 0; i < 8; i++)
        #pragma unroll
        for (int j = 0; j < 4; j++) acc[i][j] = 0.f;

    int nst = (row0 + 128) >> 5;                 // >= 4 always

    auto issue = [&](int st, int k0) {
        #pragma unroll
        for (int i = 0; i < 4; i++) {
            int idx = tid + i * 256;
            int row = idx >> 3, c16 = (idx & 7) * 4;
            CP16(s2u(&AWs(st, row, c16)), W + (size_t)(row0 + row) * Sz + k0 + c16);
        }
        #pragma unroll
        for (int i = 0; i < 2; i++) {
            int idx = tid + i * 256;
            int row = idx >> 4, c16 = (idx & 15) * 4;
            CP16(s2u(&AVs(st, row, c16)), V + (size_t)(k0 + row) * HDz + c16);
        }
        CP_COMMIT();
    };

    issue(0, 0);
    issue(1, 32);

    for (int it = 0; it < nst; it++) {
        int cur = it - (it / 3) * 3;
        if (it + 2 < nst)
            asm volatile("cp.async.wait_group 1;\n" ::: "memory");
        else
            asm volatile("cp.async.wait_group 0;\n" ::: "memory");
        __syncthreads();

        #pragma unroll
        for (int ks = 0; ks < 4; ks++) {
            int k = ks * 8;
            uint32_t afr[2][4], bfr[4][2];
            #pragma unroll
            for (int mi = 0; mi < 2; mi++) {
                int r = wm + mi * 16 + g;
                afr[mi][0] = f2tf32(AWs(cur, r, k + t));
                afr[mi][1] = f2tf32(AWs(cur, r + 8, k + t));
                afr[mi][2] = f2tf32(AWs(cur, r, k + t + 4));
                afr[mi][3] = f2tf32(AWs(cur, r + 8, k + t + 4));
            }
            #pragma unroll
            for (int ni = 0; ni < 4; ni++) {
                int c = wn + ni * 8 + g;
                bfr[ni][0] = f2tf32(AVs(cur, k + t, c));
                bfr[ni][1] = f2tf32(AVs(cur, k + t + 4, c));
            }
            #pragma unroll
            for (int mi = 0; mi < 2; mi++)
                #pragma unroll
                for (int ni = 0; ni < 4; ni++)
                    mma_tf32(acc[mi * 4 + ni], afr[mi], bfr[ni]);
        }

        if (it + 2 < nst) {
            int nx = (it + 2) - ((it + 2) / 3) * 3;
            issue(nx, (it + 2) * 32);
        }
    }

    // a feeds merge GEMM's A operand -> store tf32-rounded
    #pragma unroll
    for (int mi = 0; mi < 2; mi++) {
        #pragma unroll
        for (int ni = 0; ni < 4; ni++) {
            int r = row0 + wm + mi * 16 + g;
            int c = wn + ni * 8 + t * 2;
            *(float2*)(A + (size_t)r * Dz + c) =
                make_float2(tfr(acc[mi * 4 + ni][0]), tfr(acc[mi * 4 + ni][1]));
            *(float2*)(A + (size_t)(r + 8) * Dz + c) =
                make_float2(tfr(acc[mi * 4 + ni][2]), tfr(acc[mi * 4 + ni][3]));
        }
    }
}

// ---------------- host ------------------------------------------------------
extern "C" void kernel_launch(void* const* d_in, const int* in_sizes, int n_in,
                              void* d_out, int out_size) {
    const float* x       = (const float*)d_in[0];
    const float* qkv_w   = (const float*)d_in[1];
    const float* qkv_b   = (const float*)d_in[2];
    const float* merge_w = (const float*)d_in[3];
    const float* merge_b = (const float*)d_in[4];
    const float* mlp1_w  = (const float*)d_in[5];
    const float* mlp1_b  = (const float*)d_in[6];
    const float* mlp2_w  = (const float*)d_in[7];
    const float* mlp2_b  = (const float*)d_in[8];
    const float* n1_g    = (const float*)d_in[9];
    const float* n1_b    = (const float*)d_in[10];
    const float* n2_g    = (const float*)d_in[11];
    const float* n2_b    = (const float*)d_in[12];

    float *ln, *q, *a, *xa, *h1, *wq, *wmm, *w1, *w2;
    cudaGetSymbolAddress((void**)&ln, g_ln);
    cudaGetSymbolAddress((void**)&q,  g_q);
    cudaGetSymbolAddress((void**)&a,  g_a);
    cudaGetSymbolAddress((void**)&xa, g_xa);
    cudaGetSymbolAddress((void**)&h1, g_h1);
    cudaGetSymbolAddress((void**)&wq, g_wq);
    cudaGetSymbolAddress((void**)&wmm, g_wm);
    cudaGetSymbolAddress((void**)&w1, g_w1);
    cudaGetSymbolAddress((void**)&w2, g_w2);

    float* out     = (float*)d_out;
    float* xm      = out;                                      // [B,S,D]
    float* present = out + (size_t)Bz * Sz * Dz;               // [B,2,H,S,hd]
    float* w       = present + (size_t)Bz * 2 * Hz * Sz * HDz; // [B,H,S,S]

    const int M = Bz * Sz;   // 4096
    const int gemmSmem   = 3 * GSTG * 4;                       // 107520 B
    const int scoresSmem = (128 * 68 + 64 * 133) * 4;          // 68864 B
    const int avSmem     = 3 * AST * 4;                        // 82944 B
    static int attrSet = 0;
    if (!attrSet) {
        cudaFuncSetAttribute(tf32gemm<1>, cudaFuncAttributeMaxDynamicSharedMemorySize, gemmSmem);
        cudaFuncSetAttribute(tf32gemm<2>, cudaFuncAttributeMaxDynamicSharedMemorySize, gemmSmem);
        cudaFuncSetAttribute(tf32gemm<3>, cudaFuncAttributeMaxDynamicSharedMemorySize, gemmSmem);
        cudaFuncSetAttribute(scores_mma, cudaFuncAttributeMaxDynamicSharedMemorySize, scoresSmem);
        cudaFuncSetAttribute(av_mma, cudaFuncAttributeMaxDynamicSharedMemorySize, avSmem);
        attrSet = 1;
    }

    // 0) pre-round weights to tf32
    cvtw_k<<<(Dz * 3 * Dz) / 1024, 256>>>(qkv_w, wq);
    cvtw_k<<<(Dz * Dz) / 1024, 256>>>(merge_w, wmm);
    cvtw_k<<<(Dz * 4 * Dz) / 1024, 256>>>(mlp1_w, w1);
    cvtw_k<<<(4 * Dz * Dz) / 1024, 256>>>(mlp2_w, w2);

    // 1) ln1 (tf32-rounded)
    layernorm_k<<<M, 256>>>(x, n1_g, n1_b, ln);
    // 2) qkv gemm -> scatter q (tf32) + present (exact, output)
    tf32gemm<3><<<dim3(3 * Dz / 128, M / 128), 256, gemmSmem>>>(
        ln, wq, qkv_b, nullptr, nullptr, q, present, M, 3 * Dz, Dz, Dz, 3 * Dz, 3 * Dz);
    // 3) scores -> w region; upper tiles zero-filled here
    scores_mma<<<dim3(Sz / 128, Sz / 128, Bz * Hz), 256, scoresSmem>>>(q, present, w);
    // 4) causal softmax; writes only up to row's tile boundary
    softmax_reg<<<dim3(Sz, Bz * Hz), 256>>>(w);
    // 5) attn out = w @ v (3-stage cp.async) -> g_a (tf32-rounded)
    av_mma<<<dim3(1, Sz / 128, Bz * Hz), 256, avSmem>>>(w, present, a);
    // 6) merge gemm + residual -> xa (exact)
    tf32gemm<1><<<dim3(Dz / 128, M / 128), 256, gemmSmem>>>(
        a, wmm, merge_b, x, xa, nullptr, nullptr, M, Dz, Dz, Dz, Dz, Dz);
    // 7) ln2 (tf32-rounded)
    layernorm_k<<<M, 256>>>(xa, n2_g, n2_b, ln);
    // 8) mlp1 + gelu -> h1 (tf32-rounded)
    tf32gemm<2><<<dim3(4 * Dz / 128, M / 128), 256, gemmSmem>>>(
        ln, w1, mlp1_b, nullptr, h1, nullptr, nullptr, M, 4 * Dz, Dz, Dz, 4 * Dz, 4 * Dz);
    // 9) mlp2 + residual -> xm (output, exact)
    tf32gemm<1><<<dim3(Dz / 128, M / 128), 256, gemmSmem>>>(
        h1, w2, mlp2_b, xa, xm, nullptr, nullptr, M, Dz, 4 * Dz, 4 * Dz, Dz, Dz);
}

// round 16
// speedup vs baseline: 1.2580x; 1.0483x over previous
#include <cuda_runtime.h>
#include <math.h>
#include <stdint.h>

#define Bz 2
#define Sz 2048
#define Dz 1024
#define Hz 16
#define HDz 64

// ---------------- scratch (device globals; no allocation allowed) ----------
__device__ float g_ln[Bz * Sz * Dz];            // layernorm output (tf32-rounded)
__device__ float g_q[Bz * Hz * Sz * HDz];       // q in [B,H,S,hd] (tf32-rounded)
__device__ float g_a[Bz * Sz * Dz];             // attention output (tf32-rounded)
__device__ float g_xa[Bz * Sz * Dz];            // x + attn (exact)
__device__ float g_h1[Bz * Sz * 4 * Dz];        // mlp hidden (tf32-rounded)
__device__ float g_wq[Dz * 3 * Dz];             // tf32-rounded weights
__device__ float g_wm[Dz * Dz];
__device__ float g_w1[Dz * 4 * Dz];
__device__ float g_w2[4 * Dz * Dz];

// ---------------- helpers ---------------------------------------------------
__device__ __forceinline__ uint32_t f2tf32(float x) {
    uint32_t y;
    asm("cvt.rna.tf32.f32 %0, %1;" : "=r"(y) : "f"(x));
    return y;
}
__device__ __forceinline__ float tfr(float x) { return __uint_as_float(f2tf32(x)); }

__device__ __forceinline__ void mma_tf32(float (&d)[4], const uint32_t (&a)[4], const uint32_t (&b)[2]) {
    asm volatile("mma.sync.aligned.m16n8k8.row.col.f32.tf32.tf32.f32 "
                 "{%0,%1,%2,%3}, {%4,%5,%6,%7}, {%8,%9}, {%0,%1,%2,%3};"
                 : "+f"(d[0]), "+f"(d[1]), "+f"(d[2]), "+f"(d[3])
                 : "r"(a[0]), "r"(a[1]), "r"(a[2]), "r"(a[3]), "r"(b[0]), "r"(b[1]));
}

__device__ __forceinline__ uint32_t s2u(const void* p) {
    return (uint32_t)__cvta_generic_to_shared(p);
}
#define CP16(dst, src) asm volatile("cp.async.cg.shared.global [%0], [%1], 16;\n" :: "r"(dst), "l"(src))
#define CP_COMMIT()    asm volatile("cp.async.commit_group;\n" ::: "memory")

// ---------------- all-weights pre-round to tf32 (single launch) ------------
__global__ void cvtw_all(const float* __restrict__ s0, const float* __restrict__ s1,
                         const float* __restrict__ s2, const float* __restrict__ s3,
                         float* __restrict__ d0, float* __restrict__ d1,
                         float* __restrict__ d2, float* __restrict__ d3) {
    int i = blockIdx.x * 256 + threadIdx.x;
    const float4* s; float4* d; int j = i;
    if (j < 786432) { s = (const float4*)s0; d = (float4*)d0; }
    else if ((j -= 786432) < 262144) { s = (const float4*)s1; d = (float4*)d1; }
    else if ((j -= 262144) < 1048576) { s = (const float4*)s2; d = (float4*)d2; }
    else { j -= 1048576; s = (const float4*)s3; d = (float4*)d3; }
    float4 v = s[j];
    v.x = tfr(v.x); v.y = tfr(v.y); v.z = tfr(v.z); v.w = tfr(v.w);
    d[j] = v;
}

// ---------------- layernorm (tf32-rounded output; feeds GEMMs only) --------
__global__ void layernorm_k(const float* __restrict__ x, const float* __restrict__ g,
                            const float* __restrict__ b, float* __restrict__ y) {
    int row = blockIdx.x;
    int tid = threadIdx.x;
    const float4* xr = (const float4*)(x + (size_t)row * Dz);
    float4 v = xr[tid];
    float s  = v.x + v.y + v.z + v.w;
    float sq = v.x * v.x + v.y * v.y + v.z * v.z + v.w * v.w;

    __shared__ float shs[8], shq[8];
    for (int o = 16; o; o >>= 1) { s += __shfl_xor_sync(0xffffffffu, s, o); sq += __shfl_xor_sync(0xffffffffu, sq, o); }
    int lane = tid & 31, wid = tid >> 5;
    if (lane == 0) { shs[wid] = s; shq[wid] = sq; }
    __syncthreads();
    float ts = 0.f, tq = 0.f;
    #pragma unroll
    for (int i = 0; i < 8; i++) { ts += shs[i]; tq += shq[i]; }
    float mean = ts * (1.0f / Dz);
    float var  = tq * (1.0f / Dz) - mean * mean;
    float rstd = rsqrtf(var + 1e-5f);

    float4 gg = ((const float4*)g)[tid];
    float4 bb = ((const float4*)b)[tid];
    float4 o;
    o.x = tfr((v.x - mean) * rstd * gg.x + bb.x);
    o.y = tfr((v.y - mean) * rstd * gg.y + bb.y);
    o.z = tfr((v.z - mean) * rstd * gg.z + bb.z);
    o.w = tfr((v.w - mean) * rstd * gg.w + bb.w);
    ((float4*)(y + (size_t)row * Dz))[tid] = o;
}

// ---------------- tf32 GEMM, 3-stage cp.async, pre-rounded operands --------
__device__ __forceinline__ void wqkv(float* __restrict__ q, float* __restrict__ pres,
                                     int r, int c, float v) {
    int b = r >> 11, s = r & (Sz - 1);
    int which = c >> 10, rest = c & (Dz - 1);
    int h = rest >> 6, d = rest & 63;
    if (which == 0)
        q[(((size_t)(b * Hz + h) * Sz + s) * HDz) + d] = tfr(v);
    else
        pres[(((size_t)((b * 2 + (which - 1)) * Hz + h) * Sz + s) * HDz) + d] = v;
}

#define GSTG 8960
#define GAs(st, r, c) gsm[(st) * GSTG + (r) * 36 + (c)]
#define GBs(st, k, c) gsm[(st) * GSTG + 4608 + (k) * 136 + (c)]

template <int EPI>  // 0 bias, 1 bias+res, 2 bias+gelu(->tf32), 3 bias+scatter qkv
__global__ __launch_bounds__(256, 2)
void tf32gemm(const float* __restrict__ A, const float* __restrict__ B,
              const float* __restrict__ bias, const float* __restrict__ res,
              float* __restrict__ C, float* __restrict__ qp, float* __restrict__ pp,
              int M, int N, int K, int lda, int ldb, int ldc) {
    extern __shared__ float gsm[];

    int tid = threadIdx.x;
    int row0 = blockIdx.y * 128, col0 = blockIdx.x * 128;

    int arow = tid >> 3;
    int acol = (tid & 7) * 4;
    int brow = tid >> 5;
    int bcol = (tid & 31) * 4;

    int lane = tid & 31, wid = tid >> 5;
    int wm = (wid >> 2) * 64, wn = (wid & 3) * 32;
    int g = lane >> 2, t = lane & 3;

    const float* Abase = A + (size_t)(row0 + arow) * lda + acol;
    const float* Bbase = B + (size_t)brow * ldb + col0 + bcol;

    float acc[16][4];
    #pragma unroll
    for (int i = 0; i < 16; i++)
        #pragma unroll
        for (int j = 0; j < 4; j++) acc[i][j] = 0.f;

    int nst = K >> 5;

    auto issue = [&](int st, int k0) {
        #pragma unroll
        for (int i = 0; i < 4; i++)
            CP16(s2u(&GAs(st, arow + i * 32, acol)), Abase + (size_t)(i * 32) * lda + k0);
        #pragma unroll
        for (int p = 0; p < 4; p++)
            CP16(s2u(&GBs(st, brow + p * 8, bcol)), Bbase + (size_t)(k0 + p * 8) * ldb);
        CP_COMMIT();
    };

    issue(0, 0);
    if (nst > 1) issue(1, 32);

    for (int it = 0; it < nst; it++) {
        int cur = it - (it / 3) * 3;
        if (it + 2 < nst)
            asm volatile("cp.async.wait_group 1;\n" ::: "memory");
        else
            asm volatile("cp.async.wait_group 0;\n" ::: "memory");
        __syncthreads();

        #pragma unroll
        for (int ks = 0; ks < 4; ks++) {
            int k = ks * 8;
            uint32_t afr[4][4], bfr[4][2];
            #pragma unroll
            for (int mi = 0; mi < 4; mi++) {
                int r = wm + mi * 16 + g;
                afr[mi][0] = __float_as_uint(GAs(cur, r, k + t));
                afr[mi][1] = __float_as_uint(GAs(cur, r + 8, k + t));
                afr[mi][2] = __float_as_uint(GAs(cur, r, k + t + 4));
                afr[mi][3] = __float_as_uint(GAs(cur, r + 8, k + t + 4));
            }
            #pragma unroll
            for (int ni = 0; ni < 4; ni++) {
                int c = wn + ni * 8 + g;
                bfr[ni][0] = __float_as_uint(GBs(cur, k + t, c));
                bfr[ni][1] = __float_as_uint(GBs(cur, k + t + 4, c));
            }
            #pragma unroll
            for (int mi = 0; mi < 4; mi++)
                #pragma unroll
                for (int ni = 0; ni < 4; ni++)
                    mma_tf32(acc[mi * 4 + ni], afr[mi], bfr[ni]);
        }

        if (it + 2 < nst) {
            int nx = (it + 2) - ((it + 2) / 3) * 3;
            issue(nx, (it + 2) * 32);
        }
    }

    #pragma unroll
    for (int mi = 0; mi < 4; mi++) {
        #pragma unroll
        for (int ni = 0; ni < 4; ni++) {
            int r = row0 + wm + mi * 16 + g;
            int c = col0 + wn + ni * 8 + t * 2;
            float b0 = bias[c], b1 = bias[c + 1];
            float v0 = acc[mi * 4 + ni][0] + b0;
            float v1 = acc[mi * 4 + ni][1] + b1;
            float v2 = acc[mi * 4 + ni][2] + b0;
            float v3 = acc[mi * 4 + ni][3] + b1;
            if (EPI == 1) {
                v0 += res[(size_t)r * ldc + c];
                v1 += res[(size_t)r * ldc + c + 1];
                v2 += res[(size_t)(r + 8) * ldc + c];
                v3 += res[(size_t)(r + 8) * ldc + c + 1];
            }
            if (EPI == 2) {
                v0 = tfr(0.5f * v0 * (1.0f + erff(v0 * 0.70710678118654752f)));
                v1 = tfr(0.5f * v1 * (1.0f + erff(v1 * 0.70710678118654752f)));
                v2 = tfr(0.5f * v2 * (1.0f + erff(v2 * 0.70710678118654752f)));
                v3 = tfr(0.5f * v3 * (1.0f + erff(v3 * 0.70710678118654752f)));
            }
            if (EPI == 3) {
                wqkv(qp, pp, r, c, v0);
                wqkv(qp, pp, r, c + 1, v1);
                wqkv(qp, pp, r + 8, c, v2);
                wqkv(qp, pp, r + 8, c + 1, v3);
            } else {
                *(float2*)(C + (size_t)r * ldc + c) = make_float2(v0, v1);
                *(float2*)(C + (size_t)(r + 8) * ldc + c) = make_float2(v2, v3);
            }
        }
    }
}

// ---------------- scores via tf32 mma: W = 0.125 * Q @ K^T -----------------
#define QS(r, c) sQ[(r) * 68 + (c)]
#define KS(d, j) sK[(d) * 133 + (j)]
__global__ __launch_bounds__(256)
void scores_mma(const float* __restrict__ q, const float* __restrict__ present,
                float* __restrict__ w) {
    int row0 = blockIdx.y * 128, col0 = blockIdx.x * 128;
    if (col0 > row0 + 127) return;
    int bh = blockIdx.z;
    int b = bh >> 4, h = bh & 15;
    const float* Q  = q + (size_t)bh * Sz * HDz;
    const float* Kd = present + (size_t)((b * 2) * Hz + h) * Sz * HDz;
    float* W = w + (size_t)bh * Sz * Sz;

    extern __shared__ float smem[];
    float* sQ = smem;
    float* sK = smem + 128 * 68;

    int tid = threadIdx.x;
    int lr = tid >> 4;
    int c4 = (tid & 15) * 4;
    #pragma unroll
    for (int i = 0; i < 8; i++) {
        int r = lr + i * 16;
        float4 a = *(const float4*)(Q + (size_t)(row0 + r) * HDz + c4);
        QS(r, c4 + 0) = a.x; QS(r, c4 + 1) = a.y;       // q already tf32-rounded
        QS(r, c4 + 2) = a.z; QS(r, c4 + 3) = a.w;
        float4 kk = *(const float4*)(Kd + (size_t)(col0 + r) * HDz + c4);
        KS(c4 + 0, r) = tfr(kk.x); KS(c4 + 1, r) = tfr(kk.y);
        KS(c4 + 2, r) = tfr(kk.z); KS(c4 + 3, r) = tfr(kk.w);
    }
    __syncthreads();

    int lane = tid & 31, wid = tid >> 5;
    int wm = (wid >> 2) * 64, wn = (wid & 3) * 32;
    int g = lane >> 2, t = lane & 3;

    float acc[16][4];
    #pragma unroll
    for (int i = 0; i < 16; i++)
        #pragma unroll
        for (int j = 0; j < 4; j++) acc[i][j] = 0.f;

    #pragma unroll
    for (int ks = 0; ks < 8; ks++) {
        int k = ks * 8;
        uint32_t afr[4][4], bfr[4][2];
        #pragma unroll
        for (int mi = 0; mi < 4; mi++) {
            int r = wm + mi * 16 + g;
            afr[mi][0] = __float_as_uint(QS(r, k + t));
            afr[mi][1] = __float_as_uint(QS(r + 8, k + t));
            afr[mi][2] = __float_as_uint(QS(r, k + t + 4));
            afr[mi][3] = __float_as_uint(QS(r + 8, k + t + 4));
        }
        #pragma unroll
        for (int ni = 0; ni < 4; ni++) {
            int c = wn + ni * 8 + g;
            bfr[ni][0] = __float_as_uint(KS(k + t, c));
            bfr[ni][1] = __float_as_uint(KS(k + t + 4, c));
        }
        #pragma unroll
        for (int mi = 0; mi < 4; mi++)
            #pragma unroll
            for (int ni = 0; ni < 4; ni++)
                mma_tf32(acc[mi * 4 + ni], afr[mi], bfr[ni]);
    }

    #pragma unroll
    for (int mi = 0; mi < 4; mi++) {
        #pragma unroll
        for (int ni = 0; ni < 4; ni++) {
            int r = row0 + wm + mi * 16 + g;
            int c = col0 + wn + ni * 8 + t * 2;
            *(float2*)(W + (size_t)r * Sz + c) =
                make_float2(acc[mi * 4 + ni][0] * 0.125f, acc[mi * 4 + ni][1] * 0.125f);
            *(float2*)(W + (size_t)(r + 8) * Sz + c) =
                make_float2(acc[mi * 4 + ni][2] * 0.125f, acc[mi * 4 + ni][3] * 0.125f);
        }
    }
}

// ---------------- causal softmax, reads causal prefix only -----------------
__global__ __launch_bounds__(256)
void softmax_reg(float* __restrict__ w) {
    int row = blockIdx.x;
    int bh  = blockIdx.y;
    float* wr = w + ((size_t)bh * Sz + row) * Sz;
    int n = row + 1;
    int tid = threadIdx.x;
    int lane = tid & 31, wid = tid >> 5;
    __shared__ float sh[8];

    int j0 = tid * 4, j1 = (tid + 256) * 4;
    float4 z4 = make_float4(0.f, 0.f, 0.f, 0.f);
    float4 v0 = (j0 < n) ? ((const float4*)wr)[tid] : z4;
    float4 v1 = (j1 < n) ? ((const float4*)wr)[tid + 256] : z4;

    float m = -1e30f;
    m = (j0 + 0 < n) ? fmaxf(m, v0.x) : m;
    m = (j0 + 1 < n) ? fmaxf(m, v0.y) : m;
    m = (j0 + 2 < n) ? fmaxf(m, v0.z) : m;
    m = (j0 + 3 < n) ? fmaxf(m, v0.w) : m;
    m = (j1 + 0 < n) ? fmaxf(m, v1.x) : m;
    m = (j1 + 1 < n) ? fmaxf(m, v1.y) : m;
    m = (j1 + 2 < n) ? fmaxf(m, v1.z) : m;
    m = (j1 + 3 < n) ? fmaxf(m, v1.w) : m;
    for (int o = 16; o; o >>= 1) m = fmaxf(m, __shfl_xor_sync(0xffffffffu, m, o));
    if (lane == 0) sh[wid] = m;
    __syncthreads();
    float M = -1e30f;
    #pragma unroll
    for (int i = 0; i < 8; i++) M = fmaxf(M, sh[i]);
    __syncthreads();

    float4 p0, p1;
    p0.x = (j0 + 0 < n) ? __expf(v0.x - M) : 0.f;
    p0.y = (j0 + 1 < n) ? __expf(v0.y - M) : 0.f;
    p0.z = (j0 + 2 < n) ? __expf(v0.z - M) : 0.f;
    p0.w = (j0 + 3 < n) ? __expf(v0.w - M) : 0.f;
    p1.x = (j1 + 0 < n) ? __expf(v1.x - M) : 0.f;
    p1.y = (j1 + 1 < n) ? __expf(v1.y - M) : 0.f;
    p1.z = (j1 + 2 < n) ? __expf(v1.z - M) : 0.f;
    p1.w = (j1 + 3 < n) ? __expf(v1.w - M) : 0.f;

    float s = p0.x + p0.y + p0.z + p0.w + p1.x + p1.y + p1.z + p1.w;
    for (int o = 16; o; o >>= 1) s += __shfl_xor_sync(0xffffffffu, s, o);
    if (lane == 0) sh[wid] = s;
    __syncthreads();
    float S = 0.f;
    #pragma unroll
    for (int i = 0; i < 8; i++) S += sh[i];
    float inv = 1.0f / S;

    p0.x *= inv; p0.y *= inv; p0.z *= inv; p0.w *= inv;
    p1.x *= inv; p1.y *= inv; p1.z *= inv; p1.w *= inv;
    ((float4*)wr)[tid] = p0;
    ((float4*)wr)[tid + 256] = p1;
}

// ---------------- A = W @ V via tf32 mma, 3-stage cp.async, heavy-first ----
#define AST 6912
#define AWs(st, r, c) avsm[(st) * AST + (r) * 36 + (c)]
#define AVs(st, k, c) avsm[(st) * AST + 4608 + (k) * 72 + (c)]

__global__ __launch_bounds__(256, 2)
void av_mma(const float* __restrict__ w, const float* __restrict__ present,
            float* __restrict__ a) {
    extern __shared__ float avsm[];
    int bh = blockIdx.z;
    int b = bh >> 4, h = bh & 15;
    int row0 = ((int)gridDim.y - 1 - (int)blockIdx.y) * 128;   // heavy blocks first
    const float* W = w + (size_t)bh * Sz * Sz;
    const float* V = present + (size_t)((b * 2 + 1) * Hz + h) * Sz * HDz;
    float* A = a + ((size_t)b * Sz) * Dz + h * HDz;

    int tid = threadIdx.x;
    int lane = tid & 31, wid = tid >> 5;
    int wm = (wid >> 1) * 32, wn = (wid & 1) * 32;
    int g = lane >> 2, t = lane & 3;

    float acc[8][4];
    #pragma unroll
    for (int i = 0; i < 8; i++)
        #pragma unroll
        for (int j = 0; j < 4; j++) acc[i][j] = 0.f;

    int nst = (row0 + 128) >> 5;                 // >= 4 always

    auto issue = [&](int st, int k0) {
        #pragma unroll
        for (int i = 0; i < 4; i++) {
            int idx = tid + i * 256;
            int row = idx >> 3, c16 = (idx & 7) * 4;
            CP16(s2u(&AWs(st, row, c16)), W + (size_t)(row0 + row) * Sz + k0 + c16);
        }
        #pragma unroll
        for (int i = 0; i < 2; i++) {
            int idx = tid + i * 256;
            int row = idx >> 4, c16 = (idx & 15) * 4;
            CP16(s2u(&AVs(st, row, c16)), V + (size_t)(k0 + row) * HDz + c16);
        }
        CP_COMMIT();
    };

    issue(0, 0);
    issue(1, 32);

    for (int it = 0; it < nst; it++) {
        int cur = it - (it / 3) * 3;
        if (it + 2 < nst)
            asm volatile("cp.async.wait_group 1;\n" ::: "memory");
        else
            asm volatile("cp.async.wait_group 0;\n" ::: "memory");
        __syncthreads();

        #pragma unroll
        for (int ks = 0; ks < 4; ks++) {
            int k = ks * 8;
            uint32_t afr[2][4], bfr[4][2];
            #pragma unroll
            for (int mi = 0; mi < 2; mi++) {
                int r = wm + mi * 16 + g;
                afr[mi][0] = f2tf32(AWs(cur, r, k + t));
                afr[mi][1] = f2tf32(AWs(cur, r + 8, k + t));
                afr[mi][2] = f2tf32(AWs(cur, r, k + t + 4));
                afr[mi][3] = f2tf32(AWs(cur, r + 8, k + t + 4));
            }
            #pragma unroll
            for (int ni = 0; ni < 4; ni++) {
                int c = wn + ni * 8 + g;
                bfr[ni][0] = f2tf32(AVs(cur, k + t, c));
                bfr[ni][1] = f2tf32(AVs(cur, k + t + 4, c));
            }
            #pragma unroll
            for (int mi = 0; mi < 2; mi++)
                #pragma unroll
                for (int ni = 0; ni < 4; ni++)
                    mma_tf32(acc[mi * 4 + ni], afr[mi], bfr[ni]);
        }

        if (it + 2 < nst) {
            int nx = (it + 2) - ((it + 2) / 3) * 3;
            issue(nx, (it + 2) * 32);
        }
    }

    // a feeds merge GEMM's A operand -> store tf32-rounded
    #pragma unroll
    for (int mi = 0; mi < 2; mi++) {
        #pragma unroll
        for (int ni = 0; ni < 4; ni++) {
            int r = row0 + wm + mi * 16 + g;
            int c = wn + ni * 8 + t * 2;
            *(float2*)(A + (size_t)r * Dz + c) =
                make_float2(tfr(acc[mi * 4 + ni][0]), tfr(acc[mi * 4 + ni][1]));
            *(float2*)(A + (size_t)(r + 8) * Dz + c) =
                make_float2(tfr(acc[mi * 4 + ni][2]), tfr(acc[mi * 4 + ni][3]));
        }
    }
}

// ---------------- host ------------------------------------------------------
extern "C" void kernel_launch(void* const* d_in, const int* in_sizes, int n_in,
                              void* d_out, int out_size) {
    const float* x       = (const float*)d_in[0];
    const float* qkv_w   = (const float*)d_in[1];
    const float* qkv_b   = (const float*)d_in[2];
    const float* merge_w = (const float*)d_in[3];
    const float* merge_b = (const float*)d_in[4];
    const float* mlp1_w  = (const float*)d_in[5];
    const float* mlp1_b  = (const float*)d_in[6];
    const float* mlp2_w  = (const float*)d_in[7];
    const float* mlp2_b  = (const float*)d_in[8];
    const float* n1_g    = (const float*)d_in[9];
    const float* n1_b    = (const float*)d_in[10];
    const float* n2_g    = (const float*)d_in[11];
    const float* n2_b    = (const float*)d_in[12];

    float *ln, *q, *a, *xa, *h1, *wq, *wmm, *w1, *w2;
    cudaGetSymbolAddress((void**)&ln, g_ln);
    cudaGetSymbolAddress((void**)&q,  g_q);
    cudaGetSymbolAddress((void**)&a,  g_a);
    cudaGetSymbolAddress((void**)&xa, g_xa);
    cudaGetSymbolAddress((void**)&h1, g_h1);
    cudaGetSymbolAddress((void**)&wq, g_wq);
    cudaGetSymbolAddress((void**)&wmm, g_wm);
    cudaGetSymbolAddress((void**)&w1, g_w1);
    cudaGetSymbolAddress((void**)&w2, g_w2);

    float* out     = (float*)d_out;
    float* xm      = out;                                      // [B,S,D]
    float* present = out + (size_t)Bz * Sz * Dz;               // [B,2,H,S,hd]
    float* w       = present + (size_t)Bz * 2 * Hz * Sz * HDz; // [B,H,S,S]

    const int M = Bz * Sz;   // 4096
    const int gemmSmem   = 3 * GSTG * 4;                       // 107520 B
    const int scoresSmem = (128 * 68 + 64 * 133) * 4;          // 68864 B
    const int avSmem     = 3 * AST * 4;                        // 82944 B
    static int attrSet = 0;
    if (!attrSet) {
        cudaFuncSetAttribute(tf32gemm<1>, cudaFuncAttributeMaxDynamicSharedMemorySize, gemmSmem);
        cudaFuncSetAttribute(tf32gemm<2>, cudaFuncAttributeMaxDynamicSharedMemorySize, gemmSmem);
        cudaFuncSetAttribute(tf32gemm<3>, cudaFuncAttributeMaxDynamicSharedMemorySize, gemmSmem);
        cudaFuncSetAttribute(scores_mma, cudaFuncAttributeMaxDynamicSharedMemorySize, scoresSmem);
        cudaFuncSetAttribute(av_mma, cudaFuncAttributeMaxDynamicSharedMemorySize, avSmem);
        attrSet = 1;
    }

    // 0) pre-round all weights to tf32 (single launch)
    cvtw_all<<<(786432 + 262144 + 1048576 + 1048576) / 256, 256>>>(
        qkv_w, merge_w, mlp1_w, mlp2_w, wq, wmm, w1, w2);

    // 1) ln1 (tf32-rounded)
    layernorm_k<<<M, 256>>>(x, n1_g, n1_b, ln);
    // 2) qkv gemm -> scatter q (tf32) + present (exact, output)
    tf32gemm<3><<<dim3(3 * Dz / 128, M / 128), 256, gemmSmem>>>(
        ln, wq, qkv_b, nullptr, nullptr, q, present, M, 3 * Dz, Dz, Dz, 3 * Dz, 3 * Dz);
    // 3) scores -> w region
    scores_mma<<<dim3(Sz / 128, Sz / 128, Bz * Hz), 256, scoresSmem>>>(q, present, w);
    // 4) causal softmax in place on w
    softmax_reg<<<dim3(Sz, Bz * Hz), 256>>>(w);
    // 5) attn out = w @ v (3-stage cp.async) -> g_a (tf32-rounded)
    av_mma<<<dim3(1, Sz / 128, Bz * Hz), 256, avSmem>>>(w, present, a);
    // 6) merge gemm + residual -> xa (exact)
    tf32gemm<1><<<dim3(Dz / 128, M / 128), 256, gemmSmem>>>(
        a, wmm, merge_b, x, xa, nullptr, nullptr, M, Dz, Dz, Dz, Dz, Dz);
    // 7) ln2 (tf32-rounded)
    layernorm_k<<<M, 256>>>(xa, n2_g, n2_b, ln);
    // 8) mlp1 + gelu -> h1 (tf32-rounded)
    tf32gemm<2><<<dim3(4 * Dz / 128, M / 128), 256, gemmSmem>>>(
        ln, w1, mlp1_b, nullptr, h1, nullptr, nullptr, M, 4 * Dz, Dz, Dz, 4 * Dz, 4 * Dz);
    // 9) mlp2 + residual -> xm (output, exact)
    tf32gemm<1><<<dim3(Dz / 128, M / 128), 256, gemmSmem>>>(
        h1, w2, mlp2_b, xa, xm, nullptr, nullptr, M, Dz, 4 * Dz, 4 * Dz, Dz, Dz);
}

// round 17
// speedup vs baseline: 1.2699x; 1.0095x over previous
#include <cuda_runtime.h>
#include <math.h>
#include <stdint.h>

#define Bz 2
#define Sz 2048
#define Dz 1024
#define Hz 16
#define HDz 64

// ---------------- scratch (device globals; no allocation allowed) ----------
__device__ float g_ln[Bz * Sz * Dz];            // layernorm output (tf32-rounded)
__device__ float g_q[Bz * Hz * Sz * HDz];       // q in [B,H,S,hd] (tf32-rounded)
__device__ float g_a[Bz * Sz * Dz];             // attention output (tf32-rounded)
__device__ float g_xa[Bz * Sz * Dz];            // x + attn (exact)
__device__ float g_h1[Bz * Sz * 4 * Dz];        // mlp hidden (tf32-rounded)
__device__ float g_wq[Dz * 3 * Dz];             // tf32-rounded weights
__device__ float g_wm[Dz * Dz];
__device__ float g_w1[Dz * 4 * Dz];
__device__ float g_w2[4 * Dz * Dz];

// ---------------- helpers ---------------------------------------------------
__device__ __forceinline__ uint32_t f2tf32(float x) {
    uint32_t y;
    asm("cvt.rna.tf32.f32 %0, %1;" : "=r"(y) : "f"(x));
    return y;
}
__device__ __forceinline__ float tfr(float x) { return __uint_as_float(f2tf32(x)); }

__device__ __forceinline__ void mma_tf32(float (&d)[4], const uint32_t (&a)[4], const uint32_t (&b)[2]) {
    asm volatile("mma.sync.aligned.m16n8k8.row.col.f32.tf32.tf32.f32 "
                 "{%0,%1,%2,%3}, {%4,%5,%6,%7}, {%8,%9}, {%0,%1,%2,%3};"
                 : "+f"(d[0]), "+f"(d[1]), "+f"(d[2]), "+f"(d[3])
                 : "r"(a[0]), "r"(a[1]), "r"(a[2]), "r"(a[3]), "r"(b[0]), "r"(b[1]));
}

__device__ __forceinline__ uint32_t s2u(const void* p) {
    return (uint32_t)__cvta_generic_to_shared(p);
}
#define CP16(dst, src) asm volatile("cp.async.cg.shared.global [%0], [%1], 16;\n" :: "r"(dst), "l"(src))
#define CP_COMMIT()    asm volatile("cp.async.commit_group;\n" ::: "memory")

// ---------------- all-weights pre-round to tf32 (single launch) ------------
__global__ void cvtw_all(const float* __restrict__ s0, const float* __restrict__ s1,
                         const float* __restrict__ s2, const float* __restrict__ s3,
                         float* __restrict__ d0, float* __restrict__ d1,
                         float* __restrict__ d2, float* __restrict__ d3) {
    int i = blockIdx.x * 256 + threadIdx.x;
    const float4* s; float4* d; int j = i;
    if (j < 786432) { s = (const float4*)s0; d = (float4*)d0; }
    else if ((j -= 786432) < 262144) { s = (const float4*)s1; d = (float4*)d1; }
    else if ((j -= 262144) < 1048576) { s = (const float4*)s2; d = (float4*)d2; }
    else { j -= 1048576; s = (const float4*)s3; d = (float4*)d3; }
    float4 v = s[j];
    v.x = tfr(v.x); v.y = tfr(v.y); v.z = tfr(v.z); v.w = tfr(v.w);
    d[j] = v;
}

// ---------------- layernorm (tf32-rounded output; feeds GEMMs only) --------
__global__ void layernorm_k(const float* __restrict__ x, const float* __restrict__ g,
                            const float* __restrict__ b, float* __restrict__ y) {
    int row = blockIdx.x;
    int tid = threadIdx.x;
    const float4* xr = (const float4*)(x + (size_t)row * Dz);
    float4 v = xr[tid];
    float s  = v.x + v.y + v.z + v.w;
    float sq = v.x * v.x + v.y * v.y + v.z * v.z + v.w * v.w;

    __shared__ float shs[8], shq[8];
    for (int o = 16; o; o >>= 1) { s += __shfl_xor_sync(0xffffffffu, s, o); sq += __shfl_xor_sync(0xffffffffu, sq, o); }
    int lane = tid & 31, wid = tid >> 5;
    if (lane == 0) { shs[wid] = s; shq[wid] = sq; }
    __syncthreads();
    float ts = 0.f, tq = 0.f;
    #pragma unroll
    for (int i = 0; i < 8; i++) { ts += shs[i]; tq += shq[i]; }
    float mean = ts * (1.0f / Dz);
    float var  = tq * (1.0f / Dz) - mean * mean;
    float rstd = rsqrtf(var + 1e-5f);

    float4 gg = ((const float4*)g)[tid];
    float4 bb = ((const float4*)b)[tid];
    float4 o;
    o.x = tfr((v.x - mean) * rstd * gg.x + bb.x);
    o.y = tfr((v.y - mean) * rstd * gg.y + bb.y);
    o.z = tfr((v.z - mean) * rstd * gg.z + bb.z);
    o.w = tfr((v.w - mean) * rstd * gg.w + bb.w);
    ((float4*)(y + (size_t)row * Dz))[tid] = o;
}

// ---------------- tf32 GEMM, 3-stage cp.async, pre-rounded operands --------
// paired scatter: (c, c+1) always lands at (d, d+1) in the same head (c even)
__device__ __forceinline__ void wqkv2(float* __restrict__ q, float* __restrict__ pres,
                                      int r, int c, float v0, float v1) {
    int b = r >> 11, s = r & (Sz - 1);
    int which = c >> 10, rest = c & (Dz - 1);
    int h = rest >> 6, d = rest & 63;
    if (which == 0)
        *(float2*)&q[(((size_t)(b * Hz + h) * Sz + s) * HDz) + d] =
            make_float2(tfr(v0), tfr(v1));
    else
        *(float2*)&pres[(((size_t)((b * 2 + (which - 1)) * Hz + h) * Sz + s) * HDz) + d] =
            make_float2(v0, v1);
}

#define GSTG 8960
#define GAs(st, r, c) gsm[(st) * GSTG + (r) * 36 + (c)]
#define GBs(st, k, c) gsm[(st) * GSTG + 4608 + (k) * 136 + (c)]

template <int EPI>  // 0 bias, 1 bias+res, 2 bias+gelu(->tf32), 3 bias+scatter qkv
__global__ __launch_bounds__(256, 2)
void tf32gemm(const float* __restrict__ A, const float* __restrict__ B,
              const float* __restrict__ bias, const float* __restrict__ res,
              float* __restrict__ C, float* __restrict__ qp, float* __restrict__ pp,
              int M, int N, int K, int lda, int ldb, int ldc) {
    extern __shared__ float gsm[];

    int tid = threadIdx.x;
    int row0 = blockIdx.y * 128, col0 = blockIdx.x * 128;

    int arow = tid >> 3;
    int acol = (tid & 7) * 4;
    int brow = tid >> 5;
    int bcol = (tid & 31) * 4;

    int lane = tid & 31, wid = tid >> 5;
    int wm = (wid >> 2) * 64, wn = (wid & 3) * 32;
    int g = lane >> 2, t = lane & 3;

    const float* Abase = A + (size_t)(row0 + arow) * lda + acol;
    const float* Bbase = B + (size_t)brow * ldb + col0 + bcol;

    float acc[16][4];
    #pragma unroll
    for (int i = 0; i < 16; i++)
        #pragma unroll
        for (int j = 0; j < 4; j++) acc[i][j] = 0.f;

    int nst = K >> 5;

    auto issue = [&](int st, int k0) {
        #pragma unroll
        for (int i = 0; i < 4; i++)
            CP16(s2u(&GAs(st, arow + i * 32, acol)), Abase + (size_t)(i * 32) * lda + k0);
        #pragma unroll
        for (int p = 0; p < 4; p++)
            CP16(s2u(&GBs(st, brow + p * 8, bcol)), Bbase + (size_t)(k0 + p * 8) * ldb);
        CP_COMMIT();
    };

    issue(0, 0);
    if (nst > 1) issue(1, 32);

    for (int it = 0; it < nst; it++) {
        int cur = it - (it / 3) * 3;
        if (it + 2 < nst)
            asm volatile("cp.async.wait_group 1;\n" ::: "memory");
        else
            asm volatile("cp.async.wait_group 0;\n" ::: "memory");
        __syncthreads();

        #pragma unroll
        for (int ks = 0; ks < 4; ks++) {
            int k = ks * 8;
            uint32_t afr[4][4], bfr[4][2];
            #pragma unroll
            for (int mi = 0; mi < 4; mi++) {
                int r = wm + mi * 16 + g;
                afr[mi][0] = __float_as_uint(GAs(cur, r, k + t));
                afr[mi][1] = __float_as_uint(GAs(cur, r + 8, k + t));
                afr[mi][2] = __float_as_uint(GAs(cur, r, k + t + 4));
                afr[mi][3] = __float_as_uint(GAs(cur, r + 8, k + t + 4));
            }
            #pragma unroll
            for (int ni = 0; ni < 4; ni++) {
                int c = wn + ni * 8 + g;
                bfr[ni][0] = __float_as_uint(GBs(cur, k + t, c));
                bfr[ni][1] = __float_as_uint(GBs(cur, k + t + 4, c));
            }
            #pragma unroll
            for (int mi = 0; mi < 4; mi++)
                #pragma unroll
                for (int ni = 0; ni < 4; ni++)
                    mma_tf32(acc[mi * 4 + ni], afr[mi], bfr[ni]);
        }

        if (it + 2 < nst) {
            int nx = (it + 2) - ((it + 2) / 3) * 3;
            issue(nx, (it + 2) * 32);
        }
    }

    #pragma unroll
    for (int mi = 0; mi < 4; mi++) {
        #pragma unroll
        for (int ni = 0; ni < 4; ni++) {
            int r = row0 + wm + mi * 16 + g;
            int c = col0 + wn + ni * 8 + t * 2;
            float b0 = bias[c], b1 = bias[c + 1];
            float v0 = acc[mi * 4 + ni][0] + b0;
            float v1 = acc[mi * 4 + ni][1] + b1;
            float v2 = acc[mi * 4 + ni][2] + b0;
            float v3 = acc[mi * 4 + ni][3] + b1;
            if (EPI == 1) {
                v0 += res[(size_t)r * ldc + c];
                v1 += res[(size_t)r * ldc + c + 1];
                v2 += res[(size_t)(r + 8) * ldc + c];
                v3 += res[(size_t)(r + 8) * ldc + c + 1];
            }
            if (EPI == 2) {
                v0 = tfr(0.5f * v0 * (1.0f + erff(v0 * 0.70710678118654752f)));
                v1 = tfr(0.5f * v1 * (1.0f + erff(v1 * 0.70710678118654752f)));
                v2 = tfr(0.5f * v2 * (1.0f + erff(v2 * 0.70710678118654752f)));
                v3 = tfr(0.5f * v3 * (1.0f + erff(v3 * 0.70710678118654752f)));
            }
            if (EPI == 3) {
                wqkv2(qp, pp, r, c, v0, v1);
                wqkv2(qp, pp, r + 8, c, v2, v3);
            } else {
                *(float2*)(C + (size_t)r * ldc + c) = make_float2(v0, v1);
                *(float2*)(C + (size_t)(r + 8) * ldc + c) = make_float2(v2, v3);
            }
        }
    }
}

// ---------------- scores via tf32 mma: W = 0.125 * Q @ K^T -----------------
#define QS(r, c) sQ[(r) * 68 + (c)]
#define KS(d, j) sK[(d) * 133 + (j)]
__global__ __launch_bounds__(256)
void scores_mma(const float* __restrict__ q, const float* __restrict__ present,
                float* __restrict__ w) {
    int row0 = blockIdx.y * 128, col0 = blockIdx.x * 128;
    if (col0 > row0 + 127) return;
    int bh = blockIdx.z;
    int b = bh >> 4, h = bh & 15;
    const float* Q  = q + (size_t)bh * Sz * HDz;
    const float* Kd = present + (size_t)((b * 2) * Hz + h) * Sz * HDz;
    float* W = w + (size_t)bh * Sz * Sz;

    extern __shared__ float smem[];
    float* sQ = smem;
    float* sK = smem + 128 * 68;

    int tid = threadIdx.x;
    int lr = tid >> 4;
    int c4 = (tid & 15) * 4;
    #pragma unroll
    for (int i = 0; i < 8; i++) {
        int r = lr + i * 16;
        float4 a = *(const float4*)(Q + (size_t)(row0 + r) * HDz + c4);
        QS(r, c4 + 0) = a.x; QS(r, c4 + 1) = a.y;       // q already tf32-rounded
        QS(r, c4 + 2) = a.z; QS(r, c4 + 3) = a.w;
        float4 kk = *(const float4*)(Kd + (size_t)(col0 + r) * HDz + c4);
        KS(c4 + 0, r) = tfr(kk.x); KS(c4 + 1, r) = tfr(kk.y);
        KS(c4 + 2, r) = tfr(kk.z); KS(c4 + 3, r) = tfr(kk.w);
    }
    __syncthreads();

    int lane = tid & 31, wid = tid >> 5;
    int wm = (wid >> 2) * 64, wn = (wid & 3) * 32;
    int g = lane >> 2, t = lane & 3;

    float acc[16][4];
    #pragma unroll
    for (int i = 0; i < 16; i++)
        #pragma unroll
        for (int j = 0; j < 4; j++) acc[i][j] = 0.f;

    #pragma unroll
    for (int ks = 0; ks < 8; ks++) {
        int k = ks * 8;
        uint32_t afr[4][4], bfr[4][2];
        #pragma unroll
        for (int mi = 0; mi < 4; mi++) {
            int r = wm + mi * 16 + g;
            afr[mi][0] = __float_as_uint(QS(r, k + t));
            afr[mi][1] = __float_as_uint(QS(r + 8, k + t));
            afr[mi][2] = __float_as_uint(QS(r, k + t + 4));
            afr[mi][3] = __float_as_uint(QS(r + 8, k + t + 4));
        }
        #pragma unroll
        for (int ni = 0; ni < 4; ni++) {
            int c = wn + ni * 8 + g;
            bfr[ni][0] = __float_as_uint(KS(k + t, c));
            bfr[ni][1] = __float_as_uint(KS(k + t + 4, c));
        }
        #pragma unroll
        for (int mi = 0; mi < 4; mi++)
            #pragma unroll
            for (int ni = 0; ni < 4; ni++)
                mma_tf32(acc[mi * 4 + ni], afr[mi], bfr[ni]);
    }

    #pragma unroll
    for (int mi = 0; mi < 4; mi++) {
        #pragma unroll
        for (int ni = 0; ni < 4; ni++) {
            int r = row0 + wm + mi * 16 + g;
            int c = col0 + wn + ni * 8 + t * 2;
            *(float2*)(W + (size_t)r * Sz + c) =
                make_float2(acc[mi * 4 + ni][0] * 0.125f, acc[mi * 4 + ni][1] * 0.125f);
            *(float2*)(W + (size_t)(r + 8) * Sz + c) =
                make_float2(acc[mi * 4 + ni][2] * 0.125f, acc[mi * 4 + ni][3] * 0.125f);
        }
    }
}

// ---------------- causal softmax; vector-level predication -----------------
__global__ __launch_bounds__(256)
void softmax_reg(float* __restrict__ w) {
    int row = blockIdx.x;
    int bh  = blockIdx.y;
    float* wr = w + ((size_t)bh * Sz + row) * Sz;
    int n = row + 1;
    int tid = threadIdx.x;
    int lane = tid & 31, wid = tid >> 5;
    __shared__ float sh[8];

    int j0 = tid * 4, j1 = (tid + 256) * 4;
    float4 z4 = make_float4(0.f, 0.f, 0.f, 0.f);
    float4 v0 = (j0 < n) ? ((const float4*)wr)[tid] : z4;
    float4 v1 = (j1 < n) ? ((const float4*)wr)[tid + 256] : z4;
    bool full0 = (j0 + 3 < n), in0 = (j0 < n);
    bool full1 = (j1 + 3 < n), in1 = (j1 < n);

    float m = -1e30f;
    if (full0) {
        m = fmaxf(fmaxf(v0.x, v0.y), fmaxf(v0.z, v0.w));
    } else if (in0) {
        m = v0.x;                                 // j0 < n guaranteed
        if (j0 + 1 < n) m = fmaxf(m, v0.y);
        if (j0 + 2 < n) m = fmaxf(m, v0.z);
    }
    if (full1) {
        m = fmaxf(m, fmaxf(fmaxf(v1.x, v1.y), fmaxf(v1.z, v1.w)));
    } else if (in1) {
        m = fmaxf(m, v1.x);
        if (j1 + 1 < n) m = fmaxf(m, v1.y);
        if (j1 + 2 < n) m = fmaxf(m, v1.z);
    }
    for (int o = 16; o; o >>= 1) m = fmaxf(m, __shfl_xor_sync(0xffffffffu, m, o));
    if (lane == 0) sh[wid] = m;
    __syncthreads();
    float M = -1e30f;
    #pragma unroll
    for (int i = 0; i < 8; i++) M = fmaxf(M, sh[i]);
    __syncthreads();

    float4 p0 = z4, p1 = z4;
    if (full0) {
        p0.x = __expf(v0.x - M); p0.y = __expf(v0.y - M);
        p0.z = __expf(v0.z - M); p0.w = __expf(v0.w - M);
    } else if (in0) {
        p0.x = __expf(v0.x - M);
        if (j0 + 1 < n) p0.y = __expf(v0.y - M);
        if (j0 + 2 < n) p0.z = __expf(v0.z - M);
    }
    if (full1) {
        p1.x = __expf(v1.x - M); p1.y = __expf(v1.y - M);
        p1.z = __expf(v1.z - M); p1.w = __expf(v1.w - M);
    } else if (in1) {
        p1.x = __expf(v1.x - M);
        if (j1 + 1 < n) p1.y = __expf(v1.y - M);
        if (j1 + 2 < n) p1.z = __expf(v1.z - M);
    }

    float s = p0.x + p0.y + p0.z + p0.w + p1.x + p1.y + p1.z + p1.w;
    for (int o = 16; o; o >>= 1) s += __shfl_xor_sync(0xffffffffu, s, o);
    if (lane == 0) sh[wid] = s;
    __syncthreads();
    float S = 0.f;
    #pragma unroll
    for (int i = 0; i < 8; i++) S += sh[i];
    float inv = 1.0f / S;

    p0.x *= inv; p0.y *= inv; p0.z *= inv; p0.w *= inv;
    p1.x *= inv; p1.y *= inv; p1.z *= inv; p1.w *= inv;
    ((float4*)wr)[tid] = p0;
    ((float4*)wr)[tid + 256] = p1;
}

// ---------------- A = W @ V via tf32 mma, 3-stage cp.async, heavy-first ----
#define AST 6912
#define AWs(st, r, c) avsm[(st) * AST + (r) * 36 + (c)]
#define AVs(st, k, c) avsm[(st) * AST + 4608 + (k) * 72 + (c)]

__global__ __launch_bounds__(256, 2)
void av_mma(const float* __restrict__ w, const float* __restrict__ present,
            float* __restrict__ a) {
    extern __shared__ float avsm[];
    int bh = blockIdx.z;
    int b = bh >> 4, h = bh & 15;
    int row0 = ((int)gridDim.y - 1 - (int)blockIdx.y) * 128;   // heavy blocks first
    const float* W = w + (size_t)bh * Sz * Sz;
    const float* V = present + (size_t)((b * 2 + 1) * Hz + h) * Sz * HDz;
    float* A = a + ((size_t)b * Sz) * Dz + h * HDz;

    int tid = threadIdx.x;
    int lane = tid & 31, wid = tid >> 5;
    int wm = (wid >> 1) * 32, wn = (wid & 1) * 32;
    int g = lane >> 2, t = lane & 3;

    float acc[8][4];
    #pragma unroll
    for (int i = 0; i < 8; i++)
        #pragma unroll
        for (int j = 0; j < 4; j++) acc[i][j] = 0.f;

    int nst = (row0 + 128) >> 5;                 // >= 4 always

    auto issue = [&](int st, int k0) {
        #pragma unroll
        for (int i = 0; i < 4; i++) {
            int idx = tid + i * 256;
            int row = idx >> 3, c16 = (idx & 7) * 4;
            CP16(s2u(&AWs(st, row, c16)), W + (size_t)(row0 + row) * Sz + k0 + c16);
        }
        #pragma unroll
        for (int i = 0; i < 2; i++) {
            int idx = tid + i * 256;
            int row = idx >> 4, c16 = (idx & 15) * 4;
            CP16(s2u(&AVs(st, row, c16)), V + (size_t)(k0 + row) * HDz + c16);
        }
        CP_COMMIT();
    };

    issue(0, 0);
    issue(1, 32);

    for (int it = 0; it < nst; it++) {
        int cur = it - (it / 3) * 3;
        if (it + 2 < nst)
            asm volatile("cp.async.wait_group 1;\n" ::: "memory");
        else
            asm volatile("cp.async.wait_group 0;\n" ::: "memory");
        __syncthreads();

        #pragma unroll
        for (int ks = 0; ks < 4; ks++) {
            int k = ks * 8;
            uint32_t afr[2][4], bfr[4][2];
            #pragma unroll
            for (int mi = 0; mi < 2; mi++) {
                int r = wm + mi * 16 + g;
                afr[mi][0] = f2tf32(AWs(cur, r, k + t));
                afr[mi][1] = f2tf32(AWs(cur, r + 8, k + t));
                afr[mi][2] = f2tf32(AWs(cur, r, k + t + 4));
                afr[mi][3] = f2tf32(AWs(cur, r + 8, k + t + 4));
            }
            #pragma unroll
            for (int ni = 0; ni < 4; ni++) {
                int c = wn + ni * 8 + g;
                bfr[ni][0] = f2tf32(AVs(cur, k + t, c));
                bfr[ni][1] = f2tf32(AVs(cur, k + t + 4, c));
            }
            #pragma unroll
            for (int mi = 0; mi < 2; mi++)
                #pragma unroll
                for (int ni = 0; ni < 4; ni++)
                    mma_tf32(acc[mi * 4 + ni], afr[mi], bfr[ni]);
        }

        if (it + 2 < nst) {
            int nx = (it + 2) - ((it + 2) / 3) * 3;
            issue(nx, (it + 2) * 32);
        }
    }

    // a feeds merge GEMM's A operand -> store tf32-rounded
    #pragma unroll
    for (int mi = 0; mi < 2; mi++) {
        #pragma unroll
        for (int ni = 0; ni < 4; ni++) {
            int r = row0 + wm + mi * 16 + g;
            int c = wn + ni * 8 + t * 2;
            *(float2*)(A + (size_t)r * Dz + c) =
                make_float2(tfr(acc[mi * 4 + ni][0]), tfr(acc[mi * 4 + ni][1]));
            *(float2*)(A + (size_t)(r + 8) * Dz + c) =
                make_float2(tfr(acc[mi * 4 + ni][2]), tfr(acc[mi * 4 + ni][3]));
        }
    }
}

// ---------------- host ------------------------------------------------------
extern "C" void kernel_launch(void* const* d_in, const int* in_sizes, int n_in,
                              void* d_out, int out_size) {
    const float* x       = (const float*)d_in[0];
    const float* qkv_w   = (const float*)d_in[1];
    const float* qkv_b   = (const float*)d_in[2];
    const float* merge_w = (const float*)d_in[3];
    const float* merge_b = (const float*)d_in[4];
    const float* mlp1_w  = (const float*)d_in[5];
    const float* mlp1_b  = (const float*)d_in[6];
    const float* mlp2_w  = (const float*)d_in[7];
    const float* mlp2_b  = (const float*)d_in[8];
    const float* n1_g    = (const float*)d_in[9];
    const float* n1_b    = (const float*)d_in[10];
    const float* n2_g    = (const float*)d_in[11];
    const float* n2_b    = (const float*)d_in[12];

    float *ln, *q, *a, *xa, *h1, *wq, *wmm, *w1, *w2;
    cudaGetSymbolAddress((void**)&ln, g_ln);
    cudaGetSymbolAddress((void**)&q,  g_q);
    cudaGetSymbolAddress((void**)&a,  g_a);
    cudaGetSymbolAddress((void**)&xa, g_xa);
    cudaGetSymbolAddress((void**)&h1, g_h1);
    cudaGetSymbolAddress((void**)&wq, g_wq);
    cudaGetSymbolAddress((void**)&wmm, g_wm);
    cudaGetSymbolAddress((void**)&w1, g_w1);
    cudaGetSymbolAddress((void**)&w2, g_w2);

    float* out     = (float*)d_out;
    float* xm      = out;                                      // [B,S,D]
    float* present = out + (size_t)Bz * Sz * Dz;               // [B,2,H,S,hd]
    float* w       = present + (size_t)Bz * 2 * Hz * Sz * HDz; // [B,H,S,S]

    const int M = Bz * Sz;   // 4096
    const int gemmSmem   = 3 * GSTG * 4;                       // 107520 B
    const int scoresSmem = (128 * 68 + 64 * 133) * 4;          // 68864 B
    const int avSmem     = 3 * AST * 4;                        // 82944 B
    static int attrSet = 0;
    if (!attrSet) {
        cudaFuncSetAttribute(tf32gemm<1>, cudaFuncAttributeMaxDynamicSharedMemorySize, gemmSmem);
        cudaFuncSetAttribute(tf32gemm<2>, cudaFuncAttributeMaxDynamicSharedMemorySize, gemmSmem);
        cudaFuncSetAttribute(tf32gemm<3>, cudaFuncAttributeMaxDynamicSharedMemorySize, gemmSmem);
        cudaFuncSetAttribute(scores_mma, cudaFuncAttributeMaxDynamicSharedMemorySize, scoresSmem);
        cudaFuncSetAttribute(av_mma, cudaFuncAttributeMaxDynamicSharedMemorySize, avSmem);
        attrSet = 1;
    }

    // 0) pre-round all weights to tf32 (single launch)
    cvtw_all<<<(786432 + 262144 + 1048576 + 1048576) / 256, 256>>>(
        qkv_w, merge_w, mlp1_w, mlp2_w, wq, wmm, w1, w2);

    // 1) ln1 (tf32-rounded)
    layernorm_k<<<M, 256>>>(x, n1_g, n1_b, ln);
    // 2) qkv gemm -> scatter q (tf32) + present (exact, output)
    tf32gemm<3><<<dim3(3 * Dz / 128, M / 128), 256, gemmSmem>>>(
        ln, wq, qkv_b, nullptr, nullptr, q, present, M, 3 * Dz, Dz, Dz, 3 * Dz, 3 * Dz);
    // 3) scores -> w region
    scores_mma<<<dim3(Sz / 128, Sz / 128, Bz * Hz), 256, scoresSmem>>>(q, present, w);
    // 4) causal softmax in place on w
    softmax_reg<<<dim3(Sz, Bz * Hz), 256>>>(w);
    // 5) attn out = w @ v (3-stage cp.async) -> g_a (tf32-rounded)
    av_mma<<<dim3(1, Sz / 128, Bz * Hz), 256, avSmem>>>(w, present, a);
    // 6) merge gemm + residual -> xa (exact)
    tf32gemm<1><<<dim3(Dz / 128, M / 128), 256, gemmSmem>>>(
        a, wmm, merge_b, x, xa, nullptr, nullptr, M, Dz, Dz, Dz, Dz, Dz);
    // 7) ln2 (tf32-rounded)
    layernorm_k<<<M, 256>>>(xa, n2_g, n2_b, ln);
    // 8) mlp1 + gelu -> h1 (tf32-rounded)
    tf32gemm<2><<<dim3(4 * Dz / 128, M / 128), 256, gemmSmem>>>(
        ln, w1, mlp1_b, nullptr, h1, nullptr, nullptr, M, 4 * Dz, Dz, Dz, 4 * Dz, 4 * Dz);
    // 9) mlp2 + residual -> xm (output, exact)
    tf32gemm<1><<<dim3(Dz / 128, M / 128), 256, gemmSmem>>>(
        h1, w2, mlp2_b, xa, xm, nullptr, nullptr, M, Dz, 4 * Dz, 4 * Dz, Dz, Dz);
}